// round 15
// baseline (speedup 1.0000x reference)
#include <cuda_runtime.h>
#include <cuda_bf16.h>
#include <cuda_fp16.h>
#include <math.h>

#define BB    8
#define CIN   256
#define COUT  128
#define HH    64
#define WW    64
#define HWSZ  (HH*WW)
#define OHH   128
#define OWW   128
#define OHW   (OHH*OWW)
#define K1TOT (CIN*9)        // 2304
#define K2TOT (COUT*4)       // 512
#define SK    72             // fallback smem k-stride
#define NC1   (HH*BB)        // mdcn CTA count = 512
#define NC2   (2*OHH*BB)     // deconv CTA count = 2048

#define SWZ(o) ((o) ^ (((o) >> 3) & 0x70))
#define IDESC_F16 0x08100010u   // M=128, N=64, f16 x f16 -> f32

#if defined(__CUDA_ARCH__) && defined(__CUDA_ARCH_FEAT_SM103_ALL)
#define HAS_TC05 1
#else
#define HAS_TC05 0
#endif

// ---------------- device scratch ----------------
__device__ float g_om [BB*27*HWSZ];
__device__ float g_y1 [BB*COUT*HWSZ];
__device__ __half g_W0h[128*K1TOT];
__device__ __half g_W1h[COUT*K1TOT];
__device__ __half g_W2h[4*COUT*K2TOT];
__device__ float g_st1[2*COUT];
__device__ float g_st2[2*COUT];
__device__ float g_p1s1[COUT*NC1];
__device__ float g_p1s2[COUT*NC1];
__device__ float g_p2s1[COUT*NC2];
__device__ float g_p2s2[COUT*NC2];

// ---------------- common helpers ----------------
__device__ __forceinline__ unsigned smem_u32(const void* p) {
    unsigned a;
    asm("{.reg .u64 t; cvta.to.shared.u64 t,%1; cvt.u32.u64 %0,t;}" : "=r"(a) : "l"(p));
    return a;
}
__device__ __forceinline__ unsigned pk2h(float a, float b) {
    __half2 h = __floats2half2_rn(a, b);
    return *(unsigned*)&h;
}
__device__ __forceinline__ void cpa16(unsigned dst, const void* src) {
    asm volatile("cp.async.cg.shared.global [%0],[%1],16;" :: "r"(dst), "l"(src));
}
__device__ __forceinline__ void cpa_wait() {
    asm volatile("cp.async.commit_group;" ::: "memory");
    asm volatile("cp.async.wait_group 0;" ::: "memory");
}

#if HAS_TC05
// ---------------- tcgen05 helpers ----------------
__device__ __forceinline__ bool elect1() {
    unsigned r;
    asm volatile("{\n\t.reg .pred p;\n\telect.sync _|p,0xFFFFFFFF;\n\tselp.b32 %0,1,0,p;\n\t}" : "=r"(r));
    return r != 0;
}
__device__ __forceinline__ void mbar_init(unsigned a, unsigned c) {
    asm volatile("mbarrier.init.shared.b64 [%0],%1;" :: "r"(a), "r"(c) : "memory");
}
__device__ __forceinline__ void mbar_wait(unsigned a, unsigned p) {
    asm volatile("{\n\t.reg .pred P;\n\tLW%=:\n\t"
                 "mbarrier.try_wait.parity.acquire.cta.shared::cta.b64 P,[%0],%1;\n\t"
                 "@!P bra LW%=;\n\t}" :: "r"(a), "r"(p) : "memory");
}
__device__ __forceinline__ void tm_alloc(unsigned saddr, unsigned n) {
    asm volatile("tcgen05.alloc.cta_group::1.sync.aligned.shared::cta.b32 [%0],%1;"
                 :: "r"(saddr), "r"(n) : "memory");
}
__device__ __forceinline__ void tm_relinq() {
    asm volatile("tcgen05.relinquish_alloc_permit.cta_group::1.sync.aligned;");
}
__device__ __forceinline__ void tm_dealloc(unsigned b, unsigned n) {
    asm volatile("tcgen05.dealloc.cta_group::1.sync.aligned.b32 %0,%1;" :: "r"(b), "r"(n));
}
__device__ __forceinline__ unsigned long long mkdesc(unsigned addr) {
    return (2ull << 61) | (1ull << 46) | (64ull << 32) | (1ull << 16)
         | ((unsigned long long)(addr >> 4) & 0x3FFF);
}
__device__ __forceinline__ void mma_ss(unsigned d, unsigned long long a, unsigned long long b, unsigned en) {
    asm volatile("{\n\t.reg .pred p;\n\tsetp.ne.u32 p,%4,0;\n\t"
                 "tcgen05.mma.cta_group::1.kind::f16 [%0], %1, %2, %3, {%5,%5,%5,%5}, p;\n\t}"
                 :: "r"(d), "l"(a), "l"(b), "r"(IDESC_F16), "r"(en), "r"(0u) : "memory");
}
__device__ __forceinline__ void tc_commit(unsigned mb) {
    asm volatile("tcgen05.commit.cta_group::1.mbarrier::arrive::one.shared::cluster.b64 [%0];"
                 :: "r"(mb) : "memory");
}
__device__ __forceinline__ void fence_async() {
    asm volatile("fence.proxy.async.shared::cta;" ::: "memory");
}
__device__ __forceinline__ void tc_fence_after()  { asm volatile("tcgen05.fence::after_thread_sync;"  ::: "memory"); }
__device__ __forceinline__ void tc_fence_before() { asm volatile("tcgen05.fence::before_thread_sync;" ::: "memory"); }
__device__ __forceinline__ void ldtm_wait() { asm volatile("tcgen05.wait::ld.sync.aligned;" ::: "memory"); }

#define LDTM32(r, addr) \
    asm volatile("tcgen05.ld.sync.aligned.32x32b.x32.b32 " \
        "{%0,%1,%2,%3,%4,%5,%6,%7,%8,%9,%10,%11,%12,%13,%14,%15," \
        "%16,%17,%18,%19,%20,%21,%22,%23,%24,%25,%26,%27,%28,%29,%30,%31},[%32];" \
        : "=r"((r)[0]),"=r"((r)[1]),"=r"((r)[2]),"=r"((r)[3]),"=r"((r)[4]),"=r"((r)[5]),"=r"((r)[6]),"=r"((r)[7]), \
          "=r"((r)[8]),"=r"((r)[9]),"=r"((r)[10]),"=r"((r)[11]),"=r"((r)[12]),"=r"((r)[13]),"=r"((r)[14]),"=r"((r)[15]), \
          "=r"((r)[16]),"=r"((r)[17]),"=r"((r)[18]),"=r"((r)[19]),"=r"((r)[20]),"=r"((r)[21]),"=r"((r)[22]),"=r"((r)[23]), \
          "=r"((r)[24]),"=r"((r)[25]),"=r"((r)[26]),"=r"((r)[27]),"=r"((r)[28]),"=r"((r)[29]),"=r"((r)[30]),"=r"((r)[31]) \
        : "r"(addr))
#else
// ---------------- fallback helpers (never selected on GB300) ----------------
__device__ __forceinline__ void ldm4(unsigned addr, unsigned r[4]) {
    asm volatile("ldmatrix.sync.aligned.m8n8.x4.shared.b16 {%0,%1,%2,%3},[%4];"
                 : "=r"(r[0]), "=r"(r[1]), "=r"(r[2]), "=r"(r[3]) : "r"(addr));
}
__device__ __forceinline__ void mma16816(float c[4], const unsigned a[4], unsigned b0, unsigned b1) {
    asm volatile("mma.sync.aligned.m16n8k16.row.col.f32.f16.f16.f32 "
                 "{%0,%1,%2,%3},{%4,%5,%6,%7},{%8,%9},{%0,%1,%2,%3};"
                 : "+f"(c[0]), "+f"(c[1]), "+f"(c[2]), "+f"(c[3])
                 : "r"(a[0]), "r"(a[1]), "r"(a[2]), "r"(a[3]), "r"(b0), "r"(b1));
}
#endif

// ---------------- weight prep (+ zero partials for fallback atomics) ----------------
__global__ void prep1_kernel(const float* __restrict__ dcn_w, const float* __restrict__ off_w) {
    int n1 = COUT*K1TOT;
    for (int idx = blockIdx.x*blockDim.x + threadIdx.x; idx < n1; idx += gridDim.x*blockDim.x) {
        int oc = idx / K1TOT;
        int kp = idx - oc*K1TOT;
        int tap = kp >> 8;
        int c   = kp & 255;
        g_W1h[idx] = __float2half(dcn_w[oc*K1TOT + c*9 + tap]);
    }
    int n0 = 128*K1TOT;
    for (int idx = blockIdx.x*blockDim.x + threadIdx.x; idx < n0; idx += gridDim.x*blockDim.x) {
        int oc = idx / K1TOT;
        int kp = idx - oc*K1TOT;
        int tap = kp >> 8;
        int c   = kp & 255;
        float v = (oc < 27) ? off_w[oc*K1TOT + c*9 + tap] : 0.f;
        g_W0h[idx] = __float2half(v);
    }
#if !HAS_TC05
    for (int idx = blockIdx.x*blockDim.x + threadIdx.x; idx < COUT*NC1; idx += gridDim.x*blockDim.x) {
        g_p1s1[idx] = 0.f; g_p1s2[idx] = 0.f;
    }
#endif
}
__global__ void prep2_kernel(const float* __restrict__ up_w) {
    int n2 = 4*COUT*K2TOT;
    for (int idx = blockIdx.x*blockDim.x + threadIdx.x; idx < n2; idx += gridDim.x*blockDim.x) {
        int pc = idx >> 16;
        int rem = idx & 65535;
        int o = rem >> 9;
        int k = rem & 511;
        int c = k >> 2, th = (k >> 1) & 1, tw = k & 1;
        int ph = pc >> 1, pw = pc & 1;
        g_W2h[idx] = __float2half(up_w[((c*COUT + o)*4 + (ph + 2*th))*4 + (pw + 2*tw)]);
    }
#if !HAS_TC05
    for (int idx = blockIdx.x*blockDim.x + threadIdx.x; idx < COUT*NC2; idx += gridDim.x*blockDim.x) {
        g_p2s1[idx] = 0.f; g_p2s2[idx] = 0.f;
    }
#endif
}

// ---------------- offset conv: tcgen05 fp16 GEMM, M=128 (27 used) ----------------
#define O_A    1024
#define O_B    33792
#define O_SMEM 50176

__global__ __launch_bounds__(256, 3) void offconv_kernel(const float* __restrict__ x,
                                                         const float* __restrict__ off_w,
                                                         const float* __restrict__ off_b) {
#if HAS_TC05
    extern __shared__ __align__(1024) char sm[];
    int h = blockIdx.x, b = blockIdx.y;
    int tid = threadIdx.x, wid = tid >> 5, lane = tid & 31;
    unsigned sbase = smem_u32(sm);

    if (wid == 0) { tm_alloc(sbase, 64); tm_relinq(); }
    if (tid == 0) { mbar_init(sbase + 16, 1); mbar_init(sbase + 24, 1); }
    __syncthreads();
    unsigned tmem;
    asm volatile("ld.shared.b32 %0,[%1];" : "=r"(tmem) : "r"(sbase));

    unsigned ph0 = 0, ph1 = 0;
    int px = tid & 63, kb = (tid >> 6) * 16;

    for (int ch = 0; ch < 36; ch++) {
        int buf = ch & 1;
        if (ch >= 2) {
            if (buf) { mbar_wait(sbase + 24, ph1); ph1 ^= 1; }
            else     { mbar_wait(sbase + 16, ph0); ph0 ^= 1; }
        }
        int k0 = ch * 64;
        unsigned abh = sbase + O_A + (unsigned)buf*16384u;
        for (int idx = tid; idx < 1024; idx += 256) {
            int row = idx >> 3, g = idx & 7;
            unsigned so = SWZ((unsigned)(row*128 + g*16));
            cpa16(abh + so, g_W0h + row*K1TOT + k0 + g*8);
        }
        unsigned bplane = (unsigned)buf*8192u;
        int tap = ch >> 2;
        int dy = tap/3 - 1, dx = tap - (tap/3)*3 - 1;
        int hh = h + dy, ww = px + dx;
        bool ok = (hh >= 0) && (hh < HH) && (ww >= 0) && (ww < WW);
        int c0 = (k0 & 255) + kb;
        const float* xc0 = x + ((size_t)b*CIN + c0)*HWSZ + hh*WW + ww;
#pragma unroll
        for (int half = 0; half < 2; half++) {
            float v[8];
#pragma unroll
            for (int j = 0; j < 8; j++)
                v[j] = ok ? xc0[(half*8 + j)*HWSZ] : 0.f;
#pragma unroll
            for (int g = 0; g < 2; g++) {
                unsigned so = SWZ((unsigned)(px*128 + (kb + half*8 + 4*g)*2));
                *(uint2*)(sm + (O_B + bplane + so)) =
                    make_uint2(pk2h(v[4*g], v[4*g+1]), pk2h(v[4*g+2], v[4*g+3]));
            }
        }
        cpa_wait();
        fence_async();
        __syncthreads();
        if (wid == 0 && elect1()) {
            unsigned long long dAh = mkdesc(abh);
            unsigned long long dBh = mkdesc(sbase + O_B + bplane);
#pragma unroll
            for (int ks = 0; ks < 4; ks++)
                mma_ss(tmem, dAh + ks*2, dBh + ks*2, (ch | ks) ? 1u : 0u);
            tc_commit(sbase + 16 + 8*buf);
        }
    }
    mbar_wait(sbase + 16, ph0);
    mbar_wait(sbase + 24, ph1);
    tc_fence_after();
    if (wid == 0) {
        int oc = lane;
        float bias = (oc < 27) ? off_b[oc] : 0.f;
        float* p = g_om + (((size_t)b*27 + oc)*HH + h)*WW;
        {
            unsigned r0[32];
            LDTM32(r0, tmem);
            ldtm_wait();
            if (oc < 27) {
#pragma unroll
                for (int c = 0; c < 32; c++)
                    p[c] = __uint_as_float(r0[c]) + bias;
            }
        }
        {
            unsigned r1[32];
            LDTM32(r1, tmem + 32);
            ldtm_wait();
            if (oc < 27) {
#pragma unroll
                for (int c = 0; c < 32; c++)
                    p[32 + c] = __uint_as_float(r1[c]) + bias;
            }
        }
    }
    tc_fence_before();
    __syncthreads();
    if (wid == 0) tm_dealloc(tmem, 64);
#else
    // -------- fallback: scalar fp32 --------
    __shared__ float xs[8][3][66];
    __shared__ float ws[2048];
    int h = blockIdx.x, b = blockIdx.y;
    int tid = threadIdx.x;
    int w  = tid & 63;
    int ty = tid >> 6;
    float acc[7];
#pragma unroll
    for (int i = 0; i < 7; i++) acc[i] = 0.f;

    for (int c0 = 0; c0 < CIN; c0 += 8) {
        for (int idx = tid; idx < 8*198; idx += 256) {
            int cl = idx / 198; int rem = idx - cl*198;
            int r = rem / 66;   int j = rem - r*66;
            int hh = h - 1 + r; int wwp = j - 1;
            float v = 0.f;
            if (hh >= 0 && hh < HH && wwp >= 0 && wwp < WW)
                v = x[((b*CIN + c0 + cl)*HH + hh)*WW + wwp];
            xs[cl][r][j] = v;
        }
        for (int idx = tid; idx < 8*243; idx += 256) {
            int cl = idx / 243; int t = idx - cl*243;
            ws[cl*243 + t] = off_w[((t/9)*CIN + c0 + cl)*9 + (t % 9)];
        }
        __syncthreads();
#pragma unroll
        for (int cl = 0; cl < 8; cl++) {
#pragma unroll
            for (int k2 = 0; k2 < 9; k2++) {
                float xv = xs[cl][k2/3][w + (k2 % 3)];
#pragma unroll
                for (int i = 0; i < 7; i++) {
                    int oc = ty + 4*i;
                    acc[i] += ws[cl*243 + oc*9 + k2] * xv;
                }
            }
        }
        __syncthreads();
    }
#pragma unroll
    for (int i = 0; i < 7; i++) {
        int oc = ty + 4*i;
        if (oc < 27)
            g_om[((b*27 + oc)*HH + h)*WW + w] = acc[i] + off_b[oc];
    }
#endif
}

// ---------------- mdcn: fp16, double-buffered, tap-major, fused bn1 partials ----------------
#define M_SI   32
#define M_SWT  4640
#define M_A    14336
#define M_B    47104
#define M_SMEM 73728

__global__ __launch_bounds__(256, 3)
void mdcn_kernel(const float* __restrict__ x, const float* __restrict__ dcn_b) {
#if HAS_TC05
    extern __shared__ __align__(1024) char sm[];
    ushort4* si4 = (ushort4*)(sm + M_SI);
    float4*  swt4 = (float4*)(sm + M_SWT);

    int h = blockIdx.x, b = blockIdx.y;
    int tid = threadIdx.x, wid = tid >> 5, lane = tid & 31;
    unsigned sbase = smem_u32(sm);

    if (wid == 0) { tm_alloc(sbase, 128); tm_relinq(); }
    if (tid == 0) { mbar_init(sbase + 16, 1); mbar_init(sbase + 24, 1); }

    for (int s = tid; s < 576; s += 256) {
        int k2 = s >> 6, px = s & 63;
        const float* omb = g_om + (size_t)b*27*HWSZ + h*WW + px;
        float dy = omb[(2*k2)    * HWSZ];
        float dx = omb[(2*k2 + 1)* HWSZ];
        float mv = 1.f / (1.f + expf(-omb[(18 + k2)*HWSZ]));
        float py  = (float)h + (float)(k2/3 - 1) + dy;
        float pxf = (float)px + (float)(k2%3 - 1) + dx;
        float y0f = floorf(py), x0f = floorf(pxf);
        float ly = py - y0f, lx = pxf - x0f;
        int y0 = (int)y0f, x0 = (int)x0f;
        int y1i = y0 + 1, x1i = x0 + 1;
        bool vy0 = (y0  >= 0) && (y0  < HH);
        bool vy1 = (y1i >= 0) && (y1i < HH);
        bool vx0 = (x0  >= 0) && (x0  < WW);
        bool vx1 = (x1i >= 0) && (x1i < WW);
        int cy0 = min(max(y0, 0), HH-1), cy1 = min(max(y1i, 0), HH-1);
        int cx0 = min(max(x0, 0), WW-1), cx1 = min(max(x1i, 0), WW-1);
        ushort4 iv;
        iv.x = (unsigned short)(cy0*WW + cx0);
        iv.y = (unsigned short)(cy0*WW + cx1);
        iv.z = (unsigned short)(cy1*WW + cx0);
        iv.w = (unsigned short)(cy1*WW + cx1);
        si4[s] = iv;
        float4 wv;
        wv.x = (1.f - ly)*(1.f - lx) * ((vy0 && vx0) ? mv : 0.f);
        wv.y = (1.f - ly)*lx         * ((vy0 && vx1) ? mv : 0.f);
        wv.z = ly*(1.f - lx)         * ((vy1 && vx0) ? mv : 0.f);
        wv.w = ly*lx                 * ((vy1 && vx1) ? mv : 0.f);
        swt4[s] = wv;
    }
    __syncthreads();
    unsigned tmem;
    asm volatile("ld.shared.b32 %0,[%1];" : "=r"(tmem) : "r"(sbase));

    const float* xb = x + (size_t)b*CIN*HWSZ;
    unsigned ph0 = 0, ph1 = 0;
    int px = tid & 63, kb = (tid >> 6) * 16;

    for (int ch = 0; ch < 36; ch++) {
        int buf = ch & 1;
        if (ch >= 2) {
            if (buf) { mbar_wait(sbase + 24, ph1); ph1 ^= 1; }
            else     { mbar_wait(sbase + 16, ph0); ph0 ^= 1; }
        }
        int k0 = ch * 64;
        unsigned abh = sbase + M_A + (unsigned)buf*16384u;
        for (int idx = tid; idx < 1024; idx += 256) {
            int row = idx >> 3, g = idx & 7;
            unsigned so = SWZ((unsigned)(row*128 + g*16));
            cpa16(abh + so, g_W1h + row*K1TOT + k0 + g*8);
        }
        unsigned bplane = (unsigned)buf*8192u;
        int tap = ch >> 2;
        int c0  = (k0 & 255) + kb;
        int s = (tap << 6) + px;
        ushort4 iv = si4[s];
        float4  wv = swt4[s];
        const float* xc0 = xb + c0*HWSZ;
#pragma unroll
        for (int half = 0; half < 2; half++) {
            float q0[8], q1[8], q2[8], q3[8];
#pragma unroll
            for (int j = 0; j < 8; j++) {
                const float* xc = xc0 + (half*8 + j)*HWSZ;
                q0[j] = xc[iv.x];
                q1[j] = xc[iv.y];
                q2[j] = xc[iv.z];
                q3[j] = xc[iv.w];
            }
            float v[8];
#pragma unroll
            for (int j = 0; j < 8; j++)
                v[j] = wv.x*q0[j] + wv.y*q1[j] + wv.z*q2[j] + wv.w*q3[j];
#pragma unroll
            for (int g = 0; g < 2; g++) {
                unsigned so = SWZ((unsigned)(px*128 + (kb + half*8 + 4*g)*2));
                *(uint2*)(sm + (M_B + bplane + so)) =
                    make_uint2(pk2h(v[4*g], v[4*g+1]), pk2h(v[4*g+2], v[4*g+3]));
            }
        }
        cpa_wait();
        fence_async();
        __syncthreads();
        if (wid == 0 && elect1()) {
            unsigned long long dAh = mkdesc(abh);
            unsigned long long dBh = mkdesc(sbase + M_B + bplane);
#pragma unroll
            for (int ks = 0; ks < 4; ks++)
                mma_ss(tmem, dAh + ks*2, dBh + ks*2, (ch | ks) ? 1u : 0u);
            tc_commit(sbase + 16 + 8*buf);
        }
    }
    mbar_wait(sbase + 16, ph0);
    mbar_wait(sbase + 24, ph1);
    tc_fence_after();
    if (wid < 4) {
        int oc = wid*32 + lane;
        float bias = dcn_b[oc];
        float* p = g_y1 + (((size_t)b*COUT + oc)*HH + h)*WW;
        float s1 = 0.f, s2 = 0.f;
        {
            unsigned r0[32];
            LDTM32(r0, tmem);
            ldtm_wait();
#pragma unroll
            for (int q = 0; q < 8; q++) {
                float4 w0;
                w0.x = __uint_as_float(r0[4*q+0]) + bias;
                w0.y = __uint_as_float(r0[4*q+1]) + bias;
                w0.z = __uint_as_float(r0[4*q+2]) + bias;
                w0.w = __uint_as_float(r0[4*q+3]) + bias;
                s1 += w0.x + w0.y + w0.z + w0.w;
                s2 += w0.x*w0.x + w0.y*w0.y + w0.z*w0.z + w0.w*w0.w;
                *(float4*)&p[4*q] = w0;
            }
        }
        {
            unsigned r1[32];
            LDTM32(r1, tmem + 32);
            ldtm_wait();
#pragma unroll
            for (int q = 0; q < 8; q++) {
                float4 w1;
                w1.x = __uint_as_float(r1[4*q+0]) + bias;
                w1.y = __uint_as_float(r1[4*q+1]) + bias;
                w1.z = __uint_as_float(r1[4*q+2]) + bias;
                w1.w = __uint_as_float(r1[4*q+3]) + bias;
                s1 += w1.x + w1.y + w1.z + w1.w;
                s2 += w1.x*w1.x + w1.y*w1.y + w1.z*w1.z + w1.w*w1.w;
                *(float4*)&p[32 + 4*q] = w1;
            }
        }
        int cta = b*HH + h;
        g_p1s1[oc*NC1 + cta] = s1;
        g_p1s2[oc*NC1 + cta] = s2;
    }
    tc_fence_before();
    __syncthreads();
    if (wid == 0) tm_dealloc(tmem, 128);
#else
    // -------- fallback: mma.sync f16 (tap-major) --------
    extern __shared__ __align__(16) char smx[];
    int*   si  = (int*)smx;
    float* swt = (float*)(smx + 9216);
    __half* Ah = (__half*)(smx + 18432);
    __half* Bh = (__half*)(smx + 55296);

    int h = blockIdx.x, b = blockIdx.y;
    int tid = threadIdx.x;
    int wid = tid >> 5, lane = tid & 31;
    int m0 = (wid >> 1) * 32;
    int n0 = (wid & 1) * 32;

    for (int s = tid; s < 576; s += 256) {
        int k2 = s >> 6, px = s & 63;
        const float* omb = g_om + (size_t)b*27*HWSZ + h*WW + px;
        float dy = omb[(2*k2)    * HWSZ];
        float dx = omb[(2*k2 + 1)* HWSZ];
        float mv = 1.f / (1.f + expf(-omb[(18 + k2)*HWSZ]));
        float py  = (float)h + (float)(k2/3 - 1) + dy;
        float pxf = (float)px + (float)(k2%3 - 1) + dx;
        float y0f = floorf(py), x0f = floorf(pxf);
        float ly = py - y0f, lx = pxf - x0f;
        int y0 = (int)y0f, x0 = (int)x0f;
        int y1i = y0 + 1, x1i = x0 + 1;
        bool vy0 = (y0  >= 0) && (y0  < HH);
        bool vy1 = (y1i >= 0) && (y1i < HH);
        bool vx0 = (x0  >= 0) && (x0  < WW);
        bool vx1 = (x1i >= 0) && (x1i < WW);
        int cy0 = min(max(y0, 0), HH-1), cy1 = min(max(y1i, 0), HH-1);
        int cx0 = min(max(x0, 0), WW-1), cx1 = min(max(x1i, 0), WW-1);
        si[0*576 + s] = cy0*WW + cx0;  si[1*576 + s] = cy0*WW + cx1;
        si[2*576 + s] = cy1*WW + cx0;  si[3*576 + s] = cy1*WW + cx1;
        swt[0*576 + s] = (1.f - ly)*(1.f - lx) * ((vy0 && vx0) ? mv : 0.f);
        swt[1*576 + s] = (1.f - ly)*lx         * ((vy0 && vx1) ? mv : 0.f);
        swt[2*576 + s] = ly*(1.f - lx)         * ((vy1 && vx0) ? mv : 0.f);
        swt[3*576 + s] = ly*lx                 * ((vy1 && vx1) ? mv : 0.f);
    }

    unsigned sAh = smem_u32(Ah);
    unsigned sBh = smem_u32(Bh);
    const float* xb = x + (size_t)b*CIN*HWSZ;

    float acc[2][4][4];
#pragma unroll
    for (int i = 0; i < 2; i++)
#pragma unroll
        for (int j = 0; j < 4; j++)
#pragma unroll
            for (int q = 0; q < 4; q++) acc[i][j][q] = 0.f;

    int li = lane >> 3, lr = lane & 7;

    for (int ch = 0; ch < K1TOT/64; ch++) {
        int k0 = ch * 64;
        __syncthreads();
        for (int idx = tid; idx < 2048; idx += 256) {
            int row = idx >> 4, part = idx & 15;
            *(uint2*)&Ah[row*SK + part*4] = *(const uint2*)&g_W1h[row*K1TOT + k0 + part*4];
        }
        for (int idx = tid; idx < 4096; idx += 256) {
            int kk = idx >> 6, px = idx & 63;
            int k = k0 + kk;
            int tap = k >> 8;
            int c = k & 255;
            int s = (tap << 6) + px;
            const float* xc = xb + c*HWSZ;
            float v = swt[s]*xc[si[s]] + swt[576+s]*xc[si[576+s]]
                    + swt[1152+s]*xc[si[1152+s]] + swt[1728+s]*xc[si[1728+s]];
            Bh[px*SK + kk] = __float2half(v);
        }
        __syncthreads();
#pragma unroll
        for (int ks = 0; ks < 4; ks++) {
            int kbx = ks * 16;
            unsigned ah[2][4], bhf[8];
#pragma unroll
            for (int mt = 0; mt < 2; mt++) {
                int row = m0 + mt*16 + ((li & 1) << 3) + lr;
                int col = kbx + ((li >> 1) << 3);
                ldm4(sAh + (unsigned)(row*SK + col)*2, ah[mt]);
            }
#pragma unroll
            for (int jj = 0; jj < 2; jj++) {
                int row = n0 + jj*16 + ((li >> 1) << 3) + lr;
                int col = kbx + ((li & 1) << 3);
                ldm4(sBh + (unsigned)(row*SK + col)*2, &bhf[jj*4]);
            }
#pragma unroll
            for (int mt = 0; mt < 2; mt++)
#pragma unroll
                for (int j = 0; j < 4; j++)
                    mma16816(acc[mt][j], ah[mt], bhf[2*j], bhf[2*j+1]);
        }
    }

    int g = lane >> 2, tg = lane & 3;
    int cta = b*HH + h;
#pragma unroll
    for (int mt = 0; mt < 2; mt++) {
        int ocA = m0 + mt*16 + g;
        int ocB = ocA + 8;
        float bzA = dcn_b[ocA], bzB = dcn_b[ocB];
        float* pA = g_y1 + ((size_t)(b*COUT + ocA)*HH + h)*WW;
        float* pB = g_y1 + ((size_t)(b*COUT + ocB)*HH + h)*WW;
        float sA1 = 0.f, sA2 = 0.f, sB1 = 0.f, sB2 = 0.f;
#pragma unroll
        for (int j = 0; j < 4; j++) {
            int w = n0 + j*8 + tg*2;
            float2 vA = {acc[mt][j][0] + bzA, acc[mt][j][1] + bzA};
            float2 vB = {acc[mt][j][2] + bzB, acc[mt][j][3] + bzB};
            sA1 += vA.x + vA.y; sA2 += vA.x*vA.x + vA.y*vA.y;
            sB1 += vB.x + vB.y; sB2 += vB.x*vB.x + vB.y*vB.y;
            *(float2*)&pA[w] = vA;
            *(float2*)&pB[w] = vB;
        }
        atomicAdd(&g_p1s1[ocA*NC1 + cta], sA1);
        atomicAdd(&g_p1s2[ocA*NC1 + cta], sA2);
        atomicAdd(&g_p1s1[ocB*NC1 + cta], sB1);
        atomicAdd(&g_p1s2[ocB*NC1 + cta], sB2);
    }
#endif
}

// ---------------- deconv: fp16, parity in grid, fused bn2 partials ----------------
#define D_SCS  32
#define D_SHS  544
#define D_A    2048
#define D_B    34816
#define D_SMEM 56320

__global__ __launch_bounds__(256, 3)
void deconv_kernel(float* __restrict__ out,
                   const float* __restrict__ bn1_g, const float* __restrict__ bn1_b) {
#if HAS_TC05
    extern __shared__ __align__(1024) char sm[];
    float* scs = (float*)(sm + D_SCS);
    float* shs = (float*)(sm + D_SHS);

    int par = blockIdx.x, oh = blockIdx.y, b = blockIdx.z;
    int phh = (oh + 1) & 1;
    int pw  = (par + 1) & 1;
    int pc  = phh*2 + pw;
    int IH0 = (oh + 1 - phh) >> 1;
    int tid = threadIdx.x, wid = tid >> 5, lane = tid & 31;
    unsigned sbase = smem_u32(sm);

    if (wid == 0) { tm_alloc(sbase, 128); tm_relinq(); }
    if (tid == 0) { mbar_init(sbase + 16, 1); mbar_init(sbase + 24, 1); }
    if (tid < COUT) {
        float sc = g_st1[COUT + tid] * bn1_g[tid];
        scs[tid] = sc;
        shs[tid] = bn1_b[tid] - g_st1[tid]*sc;
    }
    __syncthreads();
    unsigned tmem;
    asm volatile("ld.shared.b32 %0,[%1];" : "=r"(tmem) : "r"(sbase));

    const float* yb = g_y1 + (size_t)b*COUT*HWSZ;
    const __half* W2h = g_W2h + (size_t)pc*COUT*K2TOT;
    unsigned ph0 = 0, ph1 = 0;
    int px = tid & 63, kb = (tid >> 6) * 16;

    for (int ch = 0; ch < 8; ch++) {
        int buf = ch & 1;
        if (ch >= 2) {
            if (buf) { mbar_wait(sbase + 24, ph1); ph1 ^= 1; }
            else     { mbar_wait(sbase + 16, ph0); ph0 ^= 1; }
        }
        int k0 = ch * 64;
        unsigned abh = sbase + D_A + (unsigned)buf*16384u;
        for (int idx = tid; idx < 1024; idx += 256) {
            int row = idx >> 3, g = idx & 7;
            unsigned so = SWZ((unsigned)(row*128 + g*16));
            cpa16(abh + so, W2h + row*K2TOT + k0 + g*8);
        }
        unsigned bplane = (unsigned)buf*8192u;
#pragma unroll
        for (int half = 0; half < 2; half++) {
            float v[8];
#pragma unroll
            for (int j = 0; j < 8; j++) {
                int k = k0 + kb + half*8 + j;
                int cl = k >> 2, th = (k >> 1) & 1, tw = k & 1;
                int ih = IH0 - th;
                int iw = px + par - tw;
                bool ok = (ih >= 0) && (ih < HH) && (iw >= 0) && (iw < WW);
                float q = ok ? yb[cl*HWSZ + ih*WW + iw] : 0.f;
                float t = q*scs[cl] + shs[cl];
                v[j] = ok ? fmaxf(t, 0.f) : 0.f;
            }
#pragma unroll
            for (int g = 0; g < 2; g++) {
                unsigned so = SWZ((unsigned)(px*128 + (kb + half*8 + 4*g)*2));
                *(uint2*)(sm + (D_B + bplane + so)) =
                    make_uint2(pk2h(v[4*g], v[4*g+1]), pk2h(v[4*g+2], v[4*g+3]));
            }
        }
        cpa_wait();
        fence_async();
        __syncthreads();
        if (wid == 0 && elect1()) {
            unsigned long long dAh = mkdesc(abh);
            unsigned long long dBh = mkdesc(sbase + D_B + bplane);
#pragma unroll
            for (int ks = 0; ks < 4; ks++)
                mma_ss(tmem, dAh + ks*2, dBh + ks*2, (ch | ks) ? 1u : 0u);
            tc_commit(sbase + 16 + 8*buf);
        }
    }
    mbar_wait(sbase + 16, ph0);
    mbar_wait(sbase + 24, ph1);
    tc_fence_after();
    if (wid < 4) {
        int oc = wid*32 + lane;
        float* p = out + (((size_t)b*COUT + oc)*OHH + oh)*OWW + par;
        float s1 = 0.f, s2 = 0.f;
        {
            unsigned r0[32];
            LDTM32(r0, tmem);
            ldtm_wait();
#pragma unroll
            for (int c = 0; c < 32; c++) {
                float a0 = __uint_as_float(r0[c]);
                s1 += a0;
                s2 += a0*a0;
                p[2*c] = a0;
            }
        }
        {
            unsigned r1[32];
            LDTM32(r1, tmem + 32);
            ldtm_wait();
#pragma unroll
            for (int c = 0; c < 32; c++) {
                float a1 = __uint_as_float(r1[c]);
                s1 += a1;
                s2 += a1*a1;
                p[2*(32 + c)] = a1;
            }
        }
        int cta = (b*OHH + oh)*2 + par;
        g_p2s1[oc*NC2 + cta] = s1;
        g_p2s2[oc*NC2 + cta] = s2;
    }
    tc_fence_before();
    __syncthreads();
    if (wid == 0) tm_dealloc(tmem, 128);
#else
    // -------- fallback: mma.sync f16 --------
    extern __shared__ __align__(16) char smx[];
    float* scs = (float*)smx;
    float* shs = (float*)(smx + 512);
    __half* Ah = (__half*)(smx + 1024);
    __half* Bh = (__half*)(smx + 37888);

    int par = blockIdx.x;
    int oh = blockIdx.y, b = blockIdx.z;
    int ph = (oh + 1) & 1;
    int pw = (par + 1) & 1;
    int pc = ph*2 + pw;
    int IH0 = (oh + 1 - ph) >> 1;
    int tid = threadIdx.x;
    int wid = tid >> 5, lane = tid & 31;
    int m0 = (wid >> 1) * 32;
    int n0 = (wid & 1) * 32;

    if (tid < COUT) {
        float sc = g_st1[COUT + tid] * bn1_g[tid];
        scs[tid] = sc;
        shs[tid] = bn1_b[tid] - g_st1[tid]*sc;
    }

    const float* yb = g_y1 + (size_t)b*COUT*HWSZ;
    const __half* W2h = g_W2h + (size_t)pc*COUT*K2TOT;
    unsigned sAh = smem_u32(Ah);
    unsigned sBh = smem_u32(Bh);

    float acc[2][4][4];
#pragma unroll
    for (int i = 0; i < 2; i++)
#pragma unroll
        for (int j = 0; j < 4; j++)
#pragma unroll
            for (int q = 0; q < 4; q++) acc[i][j][q] = 0.f;

    int li = lane >> 3, lr = lane & 7;
    __syncthreads();

    for (int ch = 0; ch < K2TOT/64; ch++) {
        int k0 = ch * 64;
        if (ch) __syncthreads();
        for (int idx = tid; idx < 2048; idx += 256) {
            int row = idx >> 4, part = idx & 15;
            *(uint2*)&Ah[row*SK + part*4] = *(const uint2*)&W2h[row*K2TOT + k0 + part*4];
        }
        for (int idx = tid; idx < 4096; idx += 256) {
            int kk = idx >> 6, px = idx & 63;
            int k = k0 + kk;
            int cl = k >> 2, th = (k >> 1) & 1, tw = k & 1;
            int ih = IH0 - th;
            int iw = px + par - tw;
            float v = 0.f;
            if (ih >= 0 && ih < HH && iw >= 0 && iw < WW)
                v = fmaxf(yb[cl*HWSZ + ih*WW + iw]*scs[cl] + shs[cl], 0.f);
            Bh[px*SK + kk] = __float2half(v);
        }
        __syncthreads();
#pragma unroll
        for (int ks = 0; ks < 4; ks++) {
            int kbx = ks * 16;
            unsigned ah[2][4], bhf[8];
#pragma unroll
            for (int mt = 0; mt < 2; mt++) {
                int row = m0 + mt*16 + ((li & 1) << 3) + lr;
                int col = kbx + ((li >> 1) << 3);
                ldm4(sAh + (unsigned)(row*SK + col)*2, ah[mt]);
            }
#pragma unroll
            for (int jj = 0; jj < 2; jj++) {
                int row = n0 + jj*16 + ((li >> 1) << 3) + lr;
                int col = kbx + ((li & 1) << 3);
                ldm4(sBh + (unsigned)(row*SK + col)*2, &bhf[jj*4]);
            }
#pragma unroll
            for (int mt = 0; mt < 2; mt++)
#pragma unroll
                for (int j = 0; j < 4; j++)
                    mma16816(acc[mt][j], ah[mt], bhf[2*j], bhf[2*j+1]);
        }
    }

    int g = lane >> 2, tg = lane & 3;
    int cta = (b*OHH + oh)*2 + par;
#pragma unroll
    for (int mt = 0; mt < 2; mt++) {
        int ocA = m0 + mt*16 + g;
        int ocB = ocA + 8;
        float* pA = out + ((size_t)(b*COUT + ocA)*OHH + oh)*OWW;
        float* pB = out + ((size_t)(b*COUT + ocB)*OHH + oh)*OWW;
        float sA1 = 0.f, sA2 = 0.f, sB1 = 0.f, sB2 = 0.f;
#pragma unroll
        for (int j = 0; j < 4; j++) {
            int pxx = n0 + j*8 + tg*2;
            int ow = par + 2*pxx;
            float a0 = acc[mt][j][0], a1 = acc[mt][j][1];
            float b0 = acc[mt][j][2], b1 = acc[mt][j][3];
            sA1 += a0 + a1; sA2 += a0*a0 + a1*a1;
            sB1 += b0 + b1; sB2 += b0*b0 + b1*b1;
            pA[ow]     = a0;
            pA[ow + 2] = a1;
            pB[ow]     = b0;
            pB[ow + 2] = b1;
        }
        atomicAdd(&g_p2s1[ocA*NC2 + cta], sA1);
        atomicAdd(&g_p2s2[ocA*NC2 + cta], sA2);
        atomicAdd(&g_p2s1[ocB*NC2 + cta], sB1);
        atomicAdd(&g_p2s2[ocB*NC2 + cta], sB2);
    }
#endif
}

// ---------------- bn finalize from per-CTA partials ----------------
__global__ __launch_bounds__(256) void bn_fin_kernel(const float* __restrict__ s1a,
                                                     const float* __restrict__ s2a,
                                                     float* __restrict__ stats,
                                                     int n, float cnt) {
    int c = blockIdx.x;
    float s1 = 0.f, s2 = 0.f;
    for (int i = threadIdx.x; i < n; i += 256) {
        s1 += s1a[c*n + i];
        s2 += s2a[c*n + i];
    }
    __shared__ float r1[8], r2[8];
#pragma unroll
    for (int off = 16; off; off >>= 1) {
        s1 += __shfl_down_sync(~0u, s1, off);
        s2 += __shfl_down_sync(~0u, s2, off);
    }
    int lane = threadIdx.x & 31, wid = threadIdx.x >> 5;
    if (lane == 0) { r1[wid] = s1; r2[wid] = s2; }
    __syncthreads();
    if (wid == 0 && lane < 8) {
        s1 = r1[lane]; s2 = r2[lane];
#pragma unroll
        for (int off = 4; off; off >>= 1) {
            s1 += __shfl_down_sync(0xffu, s1, off);
            s2 += __shfl_down_sync(0xffu, s2, off);
        }
        if (lane == 0) {
            float mean = s1 / cnt;
            float var  = s2 / cnt - mean*mean;
            stats[c]        = mean;
            stats[COUT + c] = rsqrtf(var + 1e-5f);
        }
    }
}

// ---------------- bn apply + relu ----------------
__global__ __launch_bounds__(256) void bn_apply_kernel(float* __restrict__ x,
                                                       const float* __restrict__ stats,
                                                       const float* __restrict__ g,
                                                       const float* __restrict__ bta, int hw) {
    int bc = blockIdx.y;
    int c = bc & (COUT - 1);
    float sc = stats[COUT + c] * g[c];
    float sh = bta[c] - stats[c] * sc;
    float4* p = (float4*)(x + (size_t)bc * hw);
    int n4 = hw >> 2;
    for (int i = blockIdx.x*256 + threadIdx.x; i < n4; i += gridDim.x*256) {
        float4 v = p[i];
        v.x = fmaxf(v.x*sc + sh, 0.f);
        v.y = fmaxf(v.y*sc + sh, 0.f);
        v.z = fmaxf(v.z*sc + sh, 0.f);
        v.w = fmaxf(v.w*sc + sh, 0.f);
        p[i] = v;
    }
}

// ---------------- launch ----------------
extern "C" void kernel_launch(void* const* d_in, const int* in_sizes, int n_in,
                              void* d_out, int out_size) {
    const float* x     = (const float*)d_in[0];
    const float* off_w = (const float*)d_in[1];
    const float* off_b = (const float*)d_in[2];
    const float* dcn_w = (const float*)d_in[3];
    const float* dcn_b = (const float*)d_in[4];
    const float* bn1_g = (const float*)d_in[5];
    const float* bn1_b = (const float*)d_in[6];
    const float* up_w  = (const float*)d_in[7];
    const float* bn2_g = (const float*)d_in[8];
    const float* bn2_b = (const float*)d_in[9];
    float* out = (float*)d_out;

    float *st1p, *st2p, *p1s1, *p1s2, *p2s1, *p2s2;
    cudaGetSymbolAddress((void**)&st1p, g_st1);
    cudaGetSymbolAddress((void**)&st2p, g_st2);
    cudaGetSymbolAddress((void**)&p1s1, g_p1s1);
    cudaGetSymbolAddress((void**)&p1s2, g_p1s2);
    cudaGetSymbolAddress((void**)&p2s1, g_p2s1);
    cudaGetSymbolAddress((void**)&p2s2, g_p2s2);

    cudaFuncSetAttribute(offconv_kernel, cudaFuncAttributeMaxDynamicSharedMemorySize, O_SMEM);
    cudaFuncSetAttribute(mdcn_kernel,    cudaFuncAttributeMaxDynamicSharedMemorySize, M_SMEM);
    cudaFuncSetAttribute(deconv_kernel,  cudaFuncAttributeMaxDynamicSharedMemorySize, D_SMEM);

    prep1_kernel<<<128, 256>>>(dcn_w, off_w);
    prep2_kernel<<<128, 256>>>(up_w);
    offconv_kernel<<<dim3(HH, BB), 256, O_SMEM>>>(x, off_w, off_b);
    mdcn_kernel<<<dim3(HH, BB), 256, M_SMEM>>>(x, dcn_b);
    bn_fin_kernel<<<COUT, 256>>>(p1s1, p1s2, st1p, NC1, (float)(BB*HWSZ));
    deconv_kernel<<<dim3(2, OHH, BB), 256, D_SMEM>>>(out, bn1_g, bn1_b);
    bn_fin_kernel<<<COUT, 256>>>(p2s1, p2s2, st2p, NC2, (float)(BB*OHW));
    bn_apply_kernel<<<dim3(8, BB*COUT), 256>>>(out, st2p, bn2_g, bn2_b, OHW);
}

// round 16
// speedup vs baseline: 1.0216x; 1.0216x over previous
#include <cuda_runtime.h>
#include <cuda_bf16.h>
#include <cuda_fp16.h>
#include <math.h>

#define BB    8
#define CIN   256
#define COUT  128
#define HH    64
#define WW    64
#define HWSZ  (HH*WW)
#define OHH   128
#define OWW   128
#define OHW   (OHH*OWW)
#define K1TOT (CIN*9)        // 2304
#define K2TOT (COUT*4)       // 512
#define SK    72             // fallback smem k-stride
#define NC1   (HH*BB)        // mdcn CTA count = 512
#define NC2   (2*OHH*BB)     // deconv CTA count = 2048

#define SWZ(o) ((o) ^ (((o) >> 3) & 0x70))
#define IDESC_F16 0x08100010u   // M=128, N=64, f16 x f16 -> f32

#if defined(__CUDA_ARCH__) && defined(__CUDA_ARCH_FEAT_SM103_ALL)
#define HAS_TC05 1
#else
#define HAS_TC05 0
#endif

// ---------------- device scratch ----------------
__device__ float g_om [BB*27*HWSZ];
__device__ float g_y1 [BB*COUT*HWSZ];
__device__ __half g_W0h[128*K1TOT];
__device__ __half g_W1h[COUT*K1TOT];
__device__ __half g_W2h[4*COUT*K2TOT];
__device__ float g_st1[2*COUT];
__device__ float g_st2[2*COUT];
__device__ float g_p1s1[COUT*NC1];
__device__ float g_p1s2[COUT*NC1];
__device__ float g_p2s1[COUT*NC2];
__device__ float g_p2s2[COUT*NC2];

// ---------------- common helpers ----------------
__device__ __forceinline__ unsigned smem_u32(const void* p) {
    unsigned a;
    asm("{.reg .u64 t; cvta.to.shared.u64 t,%1; cvt.u32.u64 %0,t;}" : "=r"(a) : "l"(p));
    return a;
}
__device__ __forceinline__ unsigned pk2h(float a, float b) {
    __half2 h = __floats2half2_rn(a, b);
    return *(unsigned*)&h;
}
__device__ __forceinline__ void cpa16(unsigned dst, const void* src) {
    asm volatile("cp.async.cg.shared.global [%0],[%1],16;" :: "r"(dst), "l"(src));
}
__device__ __forceinline__ void cpa_wait() {
    asm volatile("cp.async.commit_group;" ::: "memory");
    asm volatile("cp.async.wait_group 0;" ::: "memory");
}

#if HAS_TC05
// ---------------- tcgen05 helpers ----------------
__device__ __forceinline__ bool elect1() {
    unsigned r;
    asm volatile("{\n\t.reg .pred p;\n\telect.sync _|p,0xFFFFFFFF;\n\tselp.b32 %0,1,0,p;\n\t}" : "=r"(r));
    return r != 0;
}
__device__ __forceinline__ void mbar_init(unsigned a, unsigned c) {
    asm volatile("mbarrier.init.shared.b64 [%0],%1;" :: "r"(a), "r"(c) : "memory");
}
__device__ __forceinline__ void mbar_wait(unsigned a, unsigned p) {
    asm volatile("{\n\t.reg .pred P;\n\tLW%=:\n\t"
                 "mbarrier.try_wait.parity.acquire.cta.shared::cta.b64 P,[%0],%1;\n\t"
                 "@!P bra LW%=;\n\t}" :: "r"(a), "r"(p) : "memory");
}
__device__ __forceinline__ void tm_alloc(unsigned saddr, unsigned n) {
    asm volatile("tcgen05.alloc.cta_group::1.sync.aligned.shared::cta.b32 [%0],%1;"
                 :: "r"(saddr), "r"(n) : "memory");
}
__device__ __forceinline__ void tm_relinq() {
    asm volatile("tcgen05.relinquish_alloc_permit.cta_group::1.sync.aligned;");
}
__device__ __forceinline__ void tm_dealloc(unsigned b, unsigned n) {
    asm volatile("tcgen05.dealloc.cta_group::1.sync.aligned.b32 %0,%1;" :: "r"(b), "r"(n));
}
__device__ __forceinline__ unsigned long long mkdesc(unsigned addr) {
    return (2ull << 61) | (1ull << 46) | (64ull << 32) | (1ull << 16)
         | ((unsigned long long)(addr >> 4) & 0x3FFF);
}
__device__ __forceinline__ void mma_ss(unsigned d, unsigned long long a, unsigned long long b, unsigned en) {
    asm volatile("{\n\t.reg .pred p;\n\tsetp.ne.u32 p,%4,0;\n\t"
                 "tcgen05.mma.cta_group::1.kind::f16 [%0], %1, %2, %3, {%5,%5,%5,%5}, p;\n\t}"
                 :: "r"(d), "l"(a), "l"(b), "r"(IDESC_F16), "r"(en), "r"(0u) : "memory");
}
__device__ __forceinline__ void tc_commit(unsigned mb) {
    asm volatile("tcgen05.commit.cta_group::1.mbarrier::arrive::one.shared::cluster.b64 [%0];"
                 :: "r"(mb) : "memory");
}
__device__ __forceinline__ void fence_async() {
    asm volatile("fence.proxy.async.shared::cta;" ::: "memory");
}
__device__ __forceinline__ void tc_fence_after()  { asm volatile("tcgen05.fence::after_thread_sync;"  ::: "memory"); }
__device__ __forceinline__ void tc_fence_before() { asm volatile("tcgen05.fence::before_thread_sync;" ::: "memory"); }
__device__ __forceinline__ void ldtm_wait() { asm volatile("tcgen05.wait::ld.sync.aligned;" ::: "memory"); }

#define LDTM32(r, addr) \
    asm volatile("tcgen05.ld.sync.aligned.32x32b.x32.b32 " \
        "{%0,%1,%2,%3,%4,%5,%6,%7,%8,%9,%10,%11,%12,%13,%14,%15," \
        "%16,%17,%18,%19,%20,%21,%22,%23,%24,%25,%26,%27,%28,%29,%30,%31},[%32];" \
        : "=r"((r)[0]),"=r"((r)[1]),"=r"((r)[2]),"=r"((r)[3]),"=r"((r)[4]),"=r"((r)[5]),"=r"((r)[6]),"=r"((r)[7]), \
          "=r"((r)[8]),"=r"((r)[9]),"=r"((r)[10]),"=r"((r)[11]),"=r"((r)[12]),"=r"((r)[13]),"=r"((r)[14]),"=r"((r)[15]), \
          "=r"((r)[16]),"=r"((r)[17]),"=r"((r)[18]),"=r"((r)[19]),"=r"((r)[20]),"=r"((r)[21]),"=r"((r)[22]),"=r"((r)[23]), \
          "=r"((r)[24]),"=r"((r)[25]),"=r"((r)[26]),"=r"((r)[27]),"=r"((r)[28]),"=r"((r)[29]),"=r"((r)[30]),"=r"((r)[31]) \
        : "r"(addr))
#else
// ---------------- fallback helpers (never selected on GB300) ----------------
__device__ __forceinline__ void ldm4(unsigned addr, unsigned r[4]) {
    asm volatile("ldmatrix.sync.aligned.m8n8.x4.shared.b16 {%0,%1,%2,%3},[%4];"
                 : "=r"(r[0]), "=r"(r[1]), "=r"(r[2]), "=r"(r[3]) : "r"(addr));
}
__device__ __forceinline__ void mma16816(float c[4], const unsigned a[4], unsigned b0, unsigned b1) {
    asm volatile("mma.sync.aligned.m16n8k16.row.col.f32.f16.f16.f32 "
                 "{%0,%1,%2,%3},{%4,%5,%6,%7},{%8,%9},{%0,%1,%2,%3};"
                 : "+f"(c[0]), "+f"(c[1]), "+f"(c[2]), "+f"(c[3])
                 : "r"(a[0]), "r"(a[1]), "r"(a[2]), "r"(a[3]), "r"(b0), "r"(b1));
}
#endif

// ---------------- weight prep (+ zero partials for fallback atomics) ----------------
__global__ void prep1_kernel(const float* __restrict__ dcn_w, const float* __restrict__ off_w) {
    int n1 = COUT*K1TOT;
    for (int idx = blockIdx.x*blockDim.x + threadIdx.x; idx < n1; idx += gridDim.x*blockDim.x) {
        int oc = idx / K1TOT;
        int kp = idx - oc*K1TOT;
        int tap = kp >> 8;
        int c   = kp & 255;
        g_W1h[idx] = __float2half(dcn_w[oc*K1TOT + c*9 + tap]);
    }
    int n0 = 128*K1TOT;
    for (int idx = blockIdx.x*blockDim.x + threadIdx.x; idx < n0; idx += gridDim.x*blockDim.x) {
        int oc = idx / K1TOT;
        int kp = idx - oc*K1TOT;
        int tap = kp >> 8;
        int c   = kp & 255;
        float v = (oc < 27) ? off_w[oc*K1TOT + c*9 + tap] : 0.f;
        g_W0h[idx] = __float2half(v);
    }
#if !HAS_TC05
    for (int idx = blockIdx.x*blockDim.x + threadIdx.x; idx < COUT*NC1; idx += gridDim.x*blockDim.x) {
        g_p1s1[idx] = 0.f; g_p1s2[idx] = 0.f;
    }
#endif
}
__global__ void prep2_kernel(const float* __restrict__ up_w) {
    int n2 = 4*COUT*K2TOT;
    for (int idx = blockIdx.x*blockDim.x + threadIdx.x; idx < n2; idx += gridDim.x*blockDim.x) {
        int pc = idx >> 16;
        int rem = idx & 65535;
        int o = rem >> 9;
        int k = rem & 511;
        int c = k >> 2, th = (k >> 1) & 1, tw = k & 1;
        int ph = pc >> 1, pw = pc & 1;
        g_W2h[idx] = __float2half(up_w[((c*COUT + o)*4 + (ph + 2*th))*4 + (pw + 2*tw)]);
    }
#if !HAS_TC05
    for (int idx = blockIdx.x*blockDim.x + threadIdx.x; idx < COUT*NC2; idx += gridDim.x*blockDim.x) {
        g_p2s1[idx] = 0.f; g_p2s2[idx] = 0.f;
    }
#endif
}

// ---------------- offset conv: tcgen05 fp16 GEMM, M=128 (27 used) ----------------
#define O_A    1024
#define O_B    33792
#define O_SMEM 50176

__global__ __launch_bounds__(256) void offconv_kernel(const float* __restrict__ x,
                                                      const float* __restrict__ off_w,
                                                      const float* __restrict__ off_b) {
#if HAS_TC05
    extern __shared__ __align__(1024) char sm[];
    int h = blockIdx.x, b = blockIdx.y;
    int tid = threadIdx.x, wid = tid >> 5, lane = tid & 31;
    unsigned sbase = smem_u32(sm);

    if (wid == 0) { tm_alloc(sbase, 64); tm_relinq(); }
    if (tid == 0) { mbar_init(sbase + 16, 1); mbar_init(sbase + 24, 1); }
    __syncthreads();
    unsigned tmem;
    asm volatile("ld.shared.b32 %0,[%1];" : "=r"(tmem) : "r"(sbase));

    unsigned ph0 = 0, ph1 = 0;
    int px = tid & 63, kb = (tid >> 6) * 16;

    for (int ch = 0; ch < 36; ch++) {
        int buf = ch & 1;
        if (ch >= 2) {
            if (buf) { mbar_wait(sbase + 24, ph1); ph1 ^= 1; }
            else     { mbar_wait(sbase + 16, ph0); ph0 ^= 1; }
        }
        int k0 = ch * 64;
        unsigned abh = sbase + O_A + (unsigned)buf*16384u;
        for (int idx = tid; idx < 1024; idx += 256) {
            int row = idx >> 3, g = idx & 7;
            unsigned so = SWZ((unsigned)(row*128 + g*16));
            cpa16(abh + so, g_W0h + row*K1TOT + k0 + g*8);
        }
        unsigned bplane = (unsigned)buf*8192u;
        int tap = ch >> 2;
        int dy = tap/3 - 1, dx = tap - (tap/3)*3 - 1;
        int hh = h + dy, ww = px + dx;
        bool ok = (hh >= 0) && (hh < HH) && (ww >= 0) && (ww < WW);
        int c0 = (k0 & 255) + kb;
        const float* xc0 = x + ((size_t)b*CIN + c0)*HWSZ + hh*WW + ww;
#pragma unroll
        for (int half = 0; half < 2; half++) {
            float v[8];
#pragma unroll
            for (int j = 0; j < 8; j++)
                v[j] = ok ? xc0[(half*8 + j)*HWSZ] : 0.f;
#pragma unroll
            for (int g = 0; g < 2; g++) {
                unsigned so = SWZ((unsigned)(px*128 + (kb + half*8 + 4*g)*2));
                *(uint2*)(sm + (O_B + bplane + so)) =
                    make_uint2(pk2h(v[4*g], v[4*g+1]), pk2h(v[4*g+2], v[4*g+3]));
            }
        }
        cpa_wait();
        fence_async();
        __syncthreads();
        if (wid == 0 && elect1()) {
            unsigned long long dAh = mkdesc(abh);
            unsigned long long dBh = mkdesc(sbase + O_B + bplane);
#pragma unroll
            for (int ks = 0; ks < 4; ks++)
                mma_ss(tmem, dAh + ks*2, dBh + ks*2, (ch | ks) ? 1u : 0u);
            tc_commit(sbase + 16 + 8*buf);
        }
    }
    mbar_wait(sbase + 16, ph0);
    mbar_wait(sbase + 24, ph1);
    tc_fence_after();
    if (wid == 0) {
        unsigned r0[32], r1[32];
        LDTM32(r0, tmem);
        LDTM32(r1, tmem + 32);
        ldtm_wait();
        int oc = lane;
        if (oc < 27) {
            float bias = off_b[oc];
            float* p = g_om + (((size_t)b*27 + oc)*HH + h)*WW;
#pragma unroll
            for (int c = 0; c < 32; c++) {
                p[c]      = __uint_as_float(r0[c]) + bias;
                p[32 + c] = __uint_as_float(r1[c]) + bias;
            }
        }
    }
    tc_fence_before();
    __syncthreads();
    if (wid == 0) tm_dealloc(tmem, 64);
#else
    // -------- fallback: scalar fp32 --------
    __shared__ float xs[8][3][66];
    __shared__ float ws[2048];
    int h = blockIdx.x, b = blockIdx.y;
    int tid = threadIdx.x;
    int w  = tid & 63;
    int ty = tid >> 6;
    float acc[7];
#pragma unroll
    for (int i = 0; i < 7; i++) acc[i] = 0.f;

    for (int c0 = 0; c0 < CIN; c0 += 8) {
        for (int idx = tid; idx < 8*198; idx += 256) {
            int cl = idx / 198; int rem = idx - cl*198;
            int r = rem / 66;   int j = rem - r*66;
            int hh = h - 1 + r; int wwp = j - 1;
            float v = 0.f;
            if (hh >= 0 && hh < HH && wwp >= 0 && wwp < WW)
                v = x[((b*CIN + c0 + cl)*HH + hh)*WW + wwp];
            xs[cl][r][j] = v;
        }
        for (int idx = tid; idx < 8*243; idx += 256) {
            int cl = idx / 243; int t = idx - cl*243;
            ws[cl*243 + t] = off_w[((t/9)*CIN + c0 + cl)*9 + (t % 9)];
        }
        __syncthreads();
#pragma unroll
        for (int cl = 0; cl < 8; cl++) {
#pragma unroll
            for (int k2 = 0; k2 < 9; k2++) {
                float xv = xs[cl][k2/3][w + (k2 % 3)];
#pragma unroll
                for (int i = 0; i < 7; i++) {
                    int oc = ty + 4*i;
                    acc[i] += ws[cl*243 + oc*9 + k2] * xv;
                }
            }
        }
        __syncthreads();
    }
#pragma unroll
    for (int i = 0; i < 7; i++) {
        int oc = ty + 4*i;
        if (oc < 27)
            g_om[((b*27 + oc)*HH + h)*WW + w] = acc[i] + off_b[oc];
    }
#endif
}

// ---------------- mdcn: fp16, double-buffered, tap-major, fused bn1 partials ----------------
#define M_SI   32
#define M_SWT  4640
#define M_A    14336
#define M_B    47104
#define M_SMEM 73728

__global__ __launch_bounds__(256)
void mdcn_kernel(const float* __restrict__ x, const float* __restrict__ dcn_b) {
#if HAS_TC05
    extern __shared__ __align__(1024) char sm[];
    ushort4* si4 = (ushort4*)(sm + M_SI);
    float4*  swt4 = (float4*)(sm + M_SWT);

    int h = blockIdx.x, b = blockIdx.y;
    int tid = threadIdx.x, wid = tid >> 5, lane = tid & 31;
    unsigned sbase = smem_u32(sm);

    if (wid == 0) { tm_alloc(sbase, 128); tm_relinq(); }
    if (tid == 0) { mbar_init(sbase + 16, 1); mbar_init(sbase + 24, 1); }

    for (int s = tid; s < 576; s += 256) {
        int k2 = s >> 6, px = s & 63;
        const float* omb = g_om + (size_t)b*27*HWSZ + h*WW + px;
        float dy = omb[(2*k2)    * HWSZ];
        float dx = omb[(2*k2 + 1)* HWSZ];
        float mv = 1.f / (1.f + expf(-omb[(18 + k2)*HWSZ]));
        float py  = (float)h + (float)(k2/3 - 1) + dy;
        float pxf = (float)px + (float)(k2%3 - 1) + dx;
        float y0f = floorf(py), x0f = floorf(pxf);
        float ly = py - y0f, lx = pxf - x0f;
        int y0 = (int)y0f, x0 = (int)x0f;
        int y1i = y0 + 1, x1i = x0 + 1;
        bool vy0 = (y0  >= 0) && (y0  < HH);
        bool vy1 = (y1i >= 0) && (y1i < HH);
        bool vx0 = (x0  >= 0) && (x0  < WW);
        bool vx1 = (x1i >= 0) && (x1i < WW);
        int cy0 = min(max(y0, 0), HH-1), cy1 = min(max(y1i, 0), HH-1);
        int cx0 = min(max(x0, 0), WW-1), cx1 = min(max(x1i, 0), WW-1);
        ushort4 iv;
        iv.x = (unsigned short)(cy0*WW + cx0);
        iv.y = (unsigned short)(cy0*WW + cx1);
        iv.z = (unsigned short)(cy1*WW + cx0);
        iv.w = (unsigned short)(cy1*WW + cx1);
        si4[s] = iv;
        float4 wv;
        wv.x = (1.f - ly)*(1.f - lx) * ((vy0 && vx0) ? mv : 0.f);
        wv.y = (1.f - ly)*lx         * ((vy0 && vx1) ? mv : 0.f);
        wv.z = ly*(1.f - lx)         * ((vy1 && vx0) ? mv : 0.f);
        wv.w = ly*lx                 * ((vy1 && vx1) ? mv : 0.f);
        swt4[s] = wv;
    }
    __syncthreads();
    unsigned tmem;
    asm volatile("ld.shared.b32 %0,[%1];" : "=r"(tmem) : "r"(sbase));

    const float* xb = x + (size_t)b*CIN*HWSZ;
    unsigned ph0 = 0, ph1 = 0;
    int px = tid & 63, kb = (tid >> 6) * 16;

    for (int ch = 0; ch < 36; ch++) {
        int buf = ch & 1;
        if (ch >= 2) {
            if (buf) { mbar_wait(sbase + 24, ph1); ph1 ^= 1; }
            else     { mbar_wait(sbase + 16, ph0); ph0 ^= 1; }
        }
        int k0 = ch * 64;
        unsigned abh = sbase + M_A + (unsigned)buf*16384u;
        for (int idx = tid; idx < 1024; idx += 256) {
            int row = idx >> 3, g = idx & 7;
            unsigned so = SWZ((unsigned)(row*128 + g*16));
            cpa16(abh + so, g_W1h + row*K1TOT + k0 + g*8);
        }
        unsigned bplane = (unsigned)buf*8192u;
        int tap = ch >> 2;
        int c0  = (k0 & 255) + kb;
        int s = (tap << 6) + px;
        ushort4 iv = si4[s];
        float4  wv = swt4[s];
        const float* xc0 = xb + c0*HWSZ;
#pragma unroll
        for (int half = 0; half < 2; half++) {
            float q0[8], q1[8], q2[8], q3[8];
#pragma unroll
            for (int j = 0; j < 8; j++) {
                const float* xc = xc0 + (half*8 + j)*HWSZ;
                q0[j] = xc[iv.x];
                q1[j] = xc[iv.y];
                q2[j] = xc[iv.z];
                q3[j] = xc[iv.w];
            }
            float v[8];
#pragma unroll
            for (int j = 0; j < 8; j++)
                v[j] = wv.x*q0[j] + wv.y*q1[j] + wv.z*q2[j] + wv.w*q3[j];
#pragma unroll
            for (int g = 0; g < 2; g++) {
                unsigned so = SWZ((unsigned)(px*128 + (kb + half*8 + 4*g)*2));
                *(uint2*)(sm + (M_B + bplane + so)) =
                    make_uint2(pk2h(v[4*g], v[4*g+1]), pk2h(v[4*g+2], v[4*g+3]));
            }
        }
        cpa_wait();
        fence_async();
        __syncthreads();
        if (wid == 0 && elect1()) {
            unsigned long long dAh = mkdesc(abh);
            unsigned long long dBh = mkdesc(sbase + M_B + bplane);
#pragma unroll
            for (int ks = 0; ks < 4; ks++)
                mma_ss(tmem, dAh + ks*2, dBh + ks*2, (ch | ks) ? 1u : 0u);
            tc_commit(sbase + 16 + 8*buf);
        }
    }
    mbar_wait(sbase + 16, ph0);
    mbar_wait(sbase + 24, ph1);
    tc_fence_after();
    if (wid < 4) {
        unsigned r0[32], r1[32];
        LDTM32(r0, tmem);
        LDTM32(r1, tmem + 32);
        ldtm_wait();
        int oc = wid*32 + lane;
        float bias = dcn_b[oc];
        float* p = g_y1 + (((size_t)b*COUT + oc)*HH + h)*WW;
        float s1 = 0.f, s2 = 0.f;
#pragma unroll
        for (int q = 0; q < 8; q++) {
            float4 w0, w1;
            w0.x = __uint_as_float(r0[4*q+0]) + bias;
            w0.y = __uint_as_float(r0[4*q+1]) + bias;
            w0.z = __uint_as_float(r0[4*q+2]) + bias;
            w0.w = __uint_as_float(r0[4*q+3]) + bias;
            w1.x = __uint_as_float(r1[4*q+0]) + bias;
            w1.y = __uint_as_float(r1[4*q+1]) + bias;
            w1.z = __uint_as_float(r1[4*q+2]) + bias;
            w1.w = __uint_as_float(r1[4*q+3]) + bias;
            s1 += w0.x + w0.y + w0.z + w0.w + w1.x + w1.y + w1.z + w1.w;
            s2 += w0.x*w0.x + w0.y*w0.y + w0.z*w0.z + w0.w*w0.w
                + w1.x*w1.x + w1.y*w1.y + w1.z*w1.z + w1.w*w1.w;
            *(float4*)&p[4*q]      = w0;
            *(float4*)&p[32 + 4*q] = w1;
        }
        int cta = b*HH + h;
        g_p1s1[oc*NC1 + cta] = s1;
        g_p1s2[oc*NC1 + cta] = s2;
    }
    tc_fence_before();
    __syncthreads();
    if (wid == 0) tm_dealloc(tmem, 128);
#else
    // -------- fallback: mma.sync f16 (tap-major) --------
    extern __shared__ __align__(16) char smx[];
    int*   si  = (int*)smx;
    float* swt = (float*)(smx + 9216);
    __half* Ah = (__half*)(smx + 18432);
    __half* Bh = (__half*)(smx + 55296);

    int h = blockIdx.x, b = blockIdx.y;
    int tid = threadIdx.x;
    int wid = tid >> 5, lane = tid & 31;
    int m0 = (wid >> 1) * 32;
    int n0 = (wid & 1) * 32;

    for (int s = tid; s < 576; s += 256) {
        int k2 = s >> 6, px = s & 63;
        const float* omb = g_om + (size_t)b*27*HWSZ + h*WW + px;
        float dy = omb[(2*k2)    * HWSZ];
        float dx = omb[(2*k2 + 1)* HWSZ];
        float mv = 1.f / (1.f + expf(-omb[(18 + k2)*HWSZ]));
        float py  = (float)h + (float)(k2/3 - 1) + dy;
        float pxf = (float)px + (float)(k2%3 - 1) + dx;
        float y0f = floorf(py), x0f = floorf(pxf);
        float ly = py - y0f, lx = pxf - x0f;
        int y0 = (int)y0f, x0 = (int)x0f;
        int y1i = y0 + 1, x1i = x0 + 1;
        bool vy0 = (y0  >= 0) && (y0  < HH);
        bool vy1 = (y1i >= 0) && (y1i < HH);
        bool vx0 = (x0  >= 0) && (x0  < WW);
        bool vx1 = (x1i >= 0) && (x1i < WW);
        int cy0 = min(max(y0, 0), HH-1), cy1 = min(max(y1i, 0), HH-1);
        int cx0 = min(max(x0, 0), WW-1), cx1 = min(max(x1i, 0), WW-1);
        si[0*576 + s] = cy0*WW + cx0;  si[1*576 + s] = cy0*WW + cx1;
        si[2*576 + s] = cy1*WW + cx0;  si[3*576 + s] = cy1*WW + cx1;
        swt[0*576 + s] = (1.f - ly)*(1.f - lx) * ((vy0 && vx0) ? mv : 0.f);
        swt[1*576 + s] = (1.f - ly)*lx         * ((vy0 && vx1) ? mv : 0.f);
        swt[2*576 + s] = ly*(1.f - lx)         * ((vy1 && vx0) ? mv : 0.f);
        swt[3*576 + s] = ly*lx                 * ((vy1 && vx1) ? mv : 0.f);
    }

    unsigned sAh = smem_u32(Ah);
    unsigned sBh = smem_u32(Bh);
    const float* xb = x + (size_t)b*CIN*HWSZ;

    float acc[2][4][4];
#pragma unroll
    for (int i = 0; i < 2; i++)
#pragma unroll
        for (int j = 0; j < 4; j++)
#pragma unroll
            for (int q = 0; q < 4; q++) acc[i][j][q] = 0.f;

    int li = lane >> 3, lr = lane & 7;

    for (int ch = 0; ch < K1TOT/64; ch++) {
        int k0 = ch * 64;
        __syncthreads();
        for (int idx = tid; idx < 2048; idx += 256) {
            int row = idx >> 4, part = idx & 15;
            *(uint2*)&Ah[row*SK + part*4] = *(const uint2*)&g_W1h[row*K1TOT + k0 + part*4];
        }
        for (int idx = tid; idx < 4096; idx += 256) {
            int kk = idx >> 6, px = idx & 63;
            int k = k0 + kk;
            int tap = k >> 8;
            int c = k & 255;
            int s = (tap << 6) + px;
            const float* xc = xb + c*HWSZ;
            float v = swt[s]*xc[si[s]] + swt[576+s]*xc[si[576+s]]
                    + swt[1152+s]*xc[si[1152+s]] + swt[1728+s]*xc[si[1728+s]];
            Bh[px*SK + kk] = __float2half(v);
        }
        __syncthreads();
#pragma unroll
        for (int ks = 0; ks < 4; ks++) {
            int kbx = ks * 16;
            unsigned ah[2][4], bhf[8];
#pragma unroll
            for (int mt = 0; mt < 2; mt++) {
                int row = m0 + mt*16 + ((li & 1) << 3) + lr;
                int col = kbx + ((li >> 1) << 3);
                ldm4(sAh + (unsigned)(row*SK + col)*2, ah[mt]);
            }
#pragma unroll
            for (int jj = 0; jj < 2; jj++) {
                int row = n0 + jj*16 + ((li >> 1) << 3) + lr;
                int col = kbx + ((li & 1) << 3);
                ldm4(sBh + (unsigned)(row*SK + col)*2, &bhf[jj*4]);
            }
#pragma unroll
            for (int mt = 0; mt < 2; mt++)
#pragma unroll
                for (int j = 0; j < 4; j++)
                    mma16816(acc[mt][j], ah[mt], bhf[2*j], bhf[2*j+1]);
        }
    }

    int g = lane >> 2, tg = lane & 3;
    int cta = b*HH + h;
#pragma unroll
    for (int mt = 0; mt < 2; mt++) {
        int ocA = m0 + mt*16 + g;
        int ocB = ocA + 8;
        float bzA = dcn_b[ocA], bzB = dcn_b[ocB];
        float* pA = g_y1 + ((size_t)(b*COUT + ocA)*HH + h)*WW;
        float* pB = g_y1 + ((size_t)(b*COUT + ocB)*HH + h)*WW;
        float sA1 = 0.f, sA2 = 0.f, sB1 = 0.f, sB2 = 0.f;
#pragma unroll
        for (int j = 0; j < 4; j++) {
            int w = n0 + j*8 + tg*2;
            float2 vA = {acc[mt][j][0] + bzA, acc[mt][j][1] + bzA};
            float2 vB = {acc[mt][j][2] + bzB, acc[mt][j][3] + bzB};
            sA1 += vA.x + vA.y; sA2 += vA.x*vA.x + vA.y*vA.y;
            sB1 += vB.x + vB.y; sB2 += vB.x*vB.x + vB.y*vB.y;
            *(float2*)&pA[w] = vA;
            *(float2*)&pB[w] = vB;
        }
        atomicAdd(&g_p1s1[ocA*NC1 + cta], sA1);
        atomicAdd(&g_p1s2[ocA*NC1 + cta], sA2);
        atomicAdd(&g_p1s1[ocB*NC1 + cta], sB1);
        atomicAdd(&g_p1s2[ocB*NC1 + cta], sB2);
    }
#endif
}

// ---------------- deconv: fp16, parity in grid, fused bn2 partials ----------------
#define D_SCS  32
#define D_SHS  544
#define D_A    2048
#define D_B    34816
#define D_SMEM 56320

__global__ __launch_bounds__(256)
void deconv_kernel(float* __restrict__ out,
                   const float* __restrict__ bn1_g, const float* __restrict__ bn1_b) {
#if HAS_TC05
    extern __shared__ __align__(1024) char sm[];
    float* scs = (float*)(sm + D_SCS);
    float* shs = (float*)(sm + D_SHS);

    int par = blockIdx.x, oh = blockIdx.y, b = blockIdx.z;
    int phh = (oh + 1) & 1;
    int pw  = (par + 1) & 1;
    int pc  = phh*2 + pw;
    int IH0 = (oh + 1 - phh) >> 1;
    int tid = threadIdx.x, wid = tid >> 5, lane = tid & 31;
    unsigned sbase = smem_u32(sm);

    if (wid == 0) { tm_alloc(sbase, 128); tm_relinq(); }
    if (tid == 0) { mbar_init(sbase + 16, 1); mbar_init(sbase + 24, 1); }
    if (tid < COUT) {
        float sc = g_st1[COUT + tid] * bn1_g[tid];
        scs[tid] = sc;
        shs[tid] = bn1_b[tid] - g_st1[tid]*sc;
    }
    __syncthreads();
    unsigned tmem;
    asm volatile("ld.shared.b32 %0,[%1];" : "=r"(tmem) : "r"(sbase));

    const float* yb = g_y1 + (size_t)b*COUT*HWSZ;
    const __half* W2h = g_W2h + (size_t)pc*COUT*K2TOT;
    unsigned ph0 = 0, ph1 = 0;
    int px = tid & 63, kb = (tid >> 6) * 16;

    for (int ch = 0; ch < 8; ch++) {
        int buf = ch & 1;
        if (ch >= 2) {
            if (buf) { mbar_wait(sbase + 24, ph1); ph1 ^= 1; }
            else     { mbar_wait(sbase + 16, ph0); ph0 ^= 1; }
        }
        int k0 = ch * 64;
        unsigned abh = sbase + D_A + (unsigned)buf*16384u;
        for (int idx = tid; idx < 1024; idx += 256) {
            int row = idx >> 3, g = idx & 7;
            unsigned so = SWZ((unsigned)(row*128 + g*16));
            cpa16(abh + so, W2h + row*K2TOT + k0 + g*8);
        }
        unsigned bplane = (unsigned)buf*8192u;
#pragma unroll
        for (int half = 0; half < 2; half++) {
            float v[8];
#pragma unroll
            for (int j = 0; j < 8; j++) {
                int k = k0 + kb + half*8 + j;
                int cl = k >> 2, th = (k >> 1) & 1, tw = k & 1;
                int ih = IH0 - th;
                int iw = px + par - tw;
                bool ok = (ih >= 0) && (ih < HH) && (iw >= 0) && (iw < WW);
                float q = ok ? yb[cl*HWSZ + ih*WW + iw] : 0.f;
                float t = q*scs[cl] + shs[cl];
                v[j] = ok ? fmaxf(t, 0.f) : 0.f;
            }
#pragma unroll
            for (int g = 0; g < 2; g++) {
                unsigned so = SWZ((unsigned)(px*128 + (kb + half*8 + 4*g)*2));
                *(uint2*)(sm + (D_B + bplane + so)) =
                    make_uint2(pk2h(v[4*g], v[4*g+1]), pk2h(v[4*g+2], v[4*g+3]));
            }
        }
        cpa_wait();
        fence_async();
        __syncthreads();
        if (wid == 0 && elect1()) {
            unsigned long long dAh = mkdesc(abh);
            unsigned long long dBh = mkdesc(sbase + D_B + bplane);
#pragma unroll
            for (int ks = 0; ks < 4; ks++)
                mma_ss(tmem, dAh + ks*2, dBh + ks*2, (ch | ks) ? 1u : 0u);
            tc_commit(sbase + 16 + 8*buf);
        }
    }
    mbar_wait(sbase + 16, ph0);
    mbar_wait(sbase + 24, ph1);
    tc_fence_after();
    if (wid < 4) {
        unsigned r0[32], r1[32];
        LDTM32(r0, tmem);
        LDTM32(r1, tmem + 32);
        ldtm_wait();
        int oc = wid*32 + lane;
        float* p = out + (((size_t)b*COUT + oc)*OHH + oh)*OWW + par;
        float s1 = 0.f, s2 = 0.f;
#pragma unroll
        for (int c = 0; c < 32; c++) {
            float a0 = __uint_as_float(r0[c]);
            float a1 = __uint_as_float(r1[c]);
            s1 += a0 + a1;
            s2 += a0*a0 + a1*a1;
            p[2*c]        = a0;
            p[2*(32 + c)] = a1;
        }
        int cta = (b*OHH + oh)*2 + par;
        g_p2s1[oc*NC2 + cta] = s1;
        g_p2s2[oc*NC2 + cta] = s2;
    }
    tc_fence_before();
    __syncthreads();
    if (wid == 0) tm_dealloc(tmem, 128);
#else
    // -------- fallback: mma.sync f16 --------
    extern __shared__ __align__(16) char smx[];
    float* scs = (float*)smx;
    float* shs = (float*)(smx + 512);
    __half* Ah = (__half*)(smx + 1024);
    __half* Bh = (__half*)(smx + 37888);

    int par = blockIdx.x;
    int oh = blockIdx.y, b = blockIdx.z;
    int ph = (oh + 1) & 1;
    int pw = (par + 1) & 1;
    int pc = ph*2 + pw;
    int IH0 = (oh + 1 - ph) >> 1;
    int tid = threadIdx.x;
    int wid = tid >> 5, lane = tid & 31;
    int m0 = (wid >> 1) * 32;
    int n0 = (wid & 1) * 32;

    if (tid < COUT) {
        float sc = g_st1[COUT + tid] * bn1_g[tid];
        scs[tid] = sc;
        shs[tid] = bn1_b[tid] - g_st1[tid]*sc;
    }

    const float* yb = g_y1 + (size_t)b*COUT*HWSZ;
    const __half* W2h = g_W2h + (size_t)pc*COUT*K2TOT;
    unsigned sAh = smem_u32(Ah);
    unsigned sBh = smem_u32(Bh);

    float acc[2][4][4];
#pragma unroll
    for (int i = 0; i < 2; i++)
#pragma unroll
        for (int j = 0; j < 4; j++)
#pragma unroll
            for (int q = 0; q < 4; q++) acc[i][j][q] = 0.f;

    int li = lane >> 3, lr = lane & 7;
    __syncthreads();

    for (int ch = 0; ch < K2TOT/64; ch++) {
        int k0 = ch * 64;
        if (ch) __syncthreads();
        for (int idx = tid; idx < 2048; idx += 256) {
            int row = idx >> 4, part = idx & 15;
            *(uint2*)&Ah[row*SK + part*4] = *(const uint2*)&W2h[row*K2TOT + k0 + part*4];
        }
        for (int idx = tid; idx < 4096; idx += 256) {
            int kk = idx >> 6, px = idx & 63;
            int k = k0 + kk;
            int cl = k >> 2, th = (k >> 1) & 1, tw = k & 1;
            int ih = IH0 - th;
            int iw = px + par - tw;
            float v = 0.f;
            if (ih >= 0 && ih < HH && iw >= 0 && iw < WW)
                v = fmaxf(yb[cl*HWSZ + ih*WW + iw]*scs[cl] + shs[cl], 0.f);
            Bh[px*SK + kk] = __float2half(v);
        }
        __syncthreads();
#pragma unroll
        for (int ks = 0; ks < 4; ks++) {
            int kbx = ks * 16;
            unsigned ah[2][4], bhf[8];
#pragma unroll
            for (int mt = 0; mt < 2; mt++) {
                int row = m0 + mt*16 + ((li & 1) << 3) + lr;
                int col = kbx + ((li >> 1) << 3);
                ldm4(sAh + (unsigned)(row*SK + col)*2, ah[mt]);
            }
#pragma unroll
            for (int jj = 0; jj < 2; jj++) {
                int row = n0 + jj*16 + ((li >> 1) << 3) + lr;
                int col = kbx + ((li & 1) << 3);
                ldm4(sBh + (unsigned)(row*SK + col)*2, &bhf[jj*4]);
            }
#pragma unroll
            for (int mt = 0; mt < 2; mt++)
#pragma unroll
                for (int j = 0; j < 4; j++)
                    mma16816(acc[mt][j], ah[mt], bhf[2*j], bhf[2*j+1]);
        }
    }

    int g = lane >> 2, tg = lane & 3;
    int cta = (b*OHH + oh)*2 + par;
#pragma unroll
    for (int mt = 0; mt < 2; mt++) {
        int ocA = m0 + mt*16 + g;
        int ocB = ocA + 8;
        float* pA = out + ((size_t)(b*COUT + ocA)*OHH + oh)*OWW;
        float* pB = out + ((size_t)(b*COUT + ocB)*OHH + oh)*OWW;
        float sA1 = 0.f, sA2 = 0.f, sB1 = 0.f, sB2 = 0.f;
#pragma unroll
        for (int j = 0; j < 4; j++) {
            int pxx = n0 + j*8 + tg*2;
            int ow = par + 2*pxx;
            float a0 = acc[mt][j][0], a1 = acc[mt][j][1];
            float b0 = acc[mt][j][2], b1 = acc[mt][j][3];
            sA1 += a0 + a1; sA2 += a0*a0 + a1*a1;
            sB1 += b0 + b1; sB2 += b0*b0 + b1*b1;
            pA[ow]     = a0;
            pA[ow + 2] = a1;
            pB[ow]     = b0;
            pB[ow + 2] = b1;
        }
        atomicAdd(&g_p2s1[ocA*NC2 + cta], sA1);
        atomicAdd(&g_p2s2[ocA*NC2 + cta], sA2);
        atomicAdd(&g_p2s1[ocB*NC2 + cta], sB1);
        atomicAdd(&g_p2s2[ocB*NC2 + cta], sB2);
    }
#endif
}

// ---------------- bn finalize from per-CTA partials ----------------
__global__ __launch_bounds__(256) void bn_fin_kernel(const float* __restrict__ s1a,
                                                     const float* __restrict__ s2a,
                                                     float* __restrict__ stats,
                                                     int n, float cnt) {
    int c = blockIdx.x;
    float s1 = 0.f, s2 = 0.f;
    for (int i = threadIdx.x; i < n; i += 256) {
        s1 += s1a[c*n + i];
        s2 += s2a[c*n + i];
    }
    __shared__ float r1[8], r2[8];
#pragma unroll
    for (int off = 16; off; off >>= 1) {
        s1 += __shfl_down_sync(~0u, s1, off);
        s2 += __shfl_down_sync(~0u, s2, off);
    }
    int lane = threadIdx.x & 31, wid = threadIdx.x >> 5;
    if (lane == 0) { r1[wid] = s1; r2[wid] = s2; }
    __syncthreads();
    if (wid == 0 && lane < 8) {
        s1 = r1[lane]; s2 = r2[lane];
#pragma unroll
        for (int off = 4; off; off >>= 1) {
            s1 += __shfl_down_sync(0xffu, s1, off);
            s2 += __shfl_down_sync(0xffu, s2, off);
        }
        if (lane == 0) {
            float mean = s1 / cnt;
            float var  = s2 / cnt - mean*mean;
            stats[c]        = mean;
            stats[COUT + c] = rsqrtf(var + 1e-5f);
        }
    }
}

// ---------------- bn apply + relu: flat 1D, one float4/thread ----------------
__global__ __launch_bounds__(256) void bn_apply_kernel(float* __restrict__ x,
                                                       const float* __restrict__ stats,
                                                       const float* __restrict__ g,
                                                       const float* __restrict__ bta) {
    int i = blockIdx.x*256 + threadIdx.x;          // over BB*COUT*OHW/4 float4s
    int c = (i >> 12) & (COUT - 1);                // OHW/4 = 4096
    float sc = stats[COUT + c] * g[c];
    float sh = bta[c] - stats[c] * sc;
    float4* p = (float4*)x;
    float4 v = p[i];
    v.x = fmaxf(v.x*sc + sh, 0.f);
    v.y = fmaxf(v.y*sc + sh, 0.f);
    v.z = fmaxf(v.z*sc + sh, 0.f);
    v.w = fmaxf(v.w*sc + sh, 0.f);
    p[i] = v;
}

// ---------------- launch ----------------
extern "C" void kernel_launch(void* const* d_in, const int* in_sizes, int n_in,
                              void* d_out, int out_size) {
    const float* x     = (const float*)d_in[0];
    const float* off_w = (const float*)d_in[1];
    const float* off_b = (const float*)d_in[2];
    const float* dcn_w = (const float*)d_in[3];
    const float* dcn_b = (const float*)d_in[4];
    const float* bn1_g = (const float*)d_in[5];
    const float* bn1_b = (const float*)d_in[6];
    const float* up_w  = (const float*)d_in[7];
    const float* bn2_g = (const float*)d_in[8];
    const float* bn2_b = (const float*)d_in[9];
    float* out = (float*)d_out;

    float *st1p, *st2p, *p1s1, *p1s2, *p2s1, *p2s2;
    cudaGetSymbolAddress((void**)&st1p, g_st1);
    cudaGetSymbolAddress((void**)&st2p, g_st2);
    cudaGetSymbolAddress((void**)&p1s1, g_p1s1);
    cudaGetSymbolAddress((void**)&p1s2, g_p1s2);
    cudaGetSymbolAddress((void**)&p2s1, g_p2s1);
    cudaGetSymbolAddress((void**)&p2s2, g_p2s2);

    cudaFuncSetAttribute(offconv_kernel, cudaFuncAttributeMaxDynamicSharedMemorySize, O_SMEM);
    cudaFuncSetAttribute(mdcn_kernel,    cudaFuncAttributeMaxDynamicSharedMemorySize, M_SMEM);
    cudaFuncSetAttribute(deconv_kernel,  cudaFuncAttributeMaxDynamicSharedMemorySize, D_SMEM);

    prep1_kernel<<<128, 256>>>(dcn_w, off_w);
    prep2_kernel<<<128, 256>>>(up_w);
    offconv_kernel<<<dim3(HH, BB), 256, O_SMEM>>>(x, off_w, off_b);
    mdcn_kernel<<<dim3(HH, BB), 256, M_SMEM>>>(x, dcn_b);
    bn_fin_kernel<<<COUT, 256>>>(p1s1, p1s2, st1p, NC1, (float)(BB*HWSZ));
    deconv_kernel<<<dim3(2, OHH, BB), 256, D_SMEM>>>(out, bn1_g, bn1_b);
    bn_fin_kernel<<<COUT, 256>>>(p2s1, p2s2, st2p, NC2, (float)(BB*OHW));
    bn_apply_kernel<<<(BB*COUT*OHW/4 + 255)/256, 256>>>(out, st2p, bn2_g, bn2_b);
}

// round 17
// speedup vs baseline: 1.0533x; 1.0310x over previous
#include <cuda_runtime.h>
#include <cuda_bf16.h>
#include <cuda_fp16.h>
#include <math.h>

#define BB    8
#define CIN   256
#define COUT  128
#define HH    64
#define WW    64
#define HWSZ  (HH*WW)
#define OHH   128
#define OWW   128
#define OHW   (OHH*OWW)
#define K1TOT (CIN*9)        // 2304
#define K2TOT (COUT*4)       // 512
#define SK    72             // fallback smem k-stride
#define NC1   (HH/2*BB)      // mdcn CTA count = 256 (2 rows per CTA)
#define NC2   (2*OHH*BB)     // deconv CTA count = 2048

#define SWZ(o) ((o) ^ (((o) >> 3) & 0x70))
#define IDESC_F16 0x08100010u   // M=128, N=64, f16 x f16 -> f32

#if defined(__CUDA_ARCH__) && defined(__CUDA_ARCH_FEAT_SM103_ALL)
#define HAS_TC05 1
#else
#define HAS_TC05 0
#endif

// ---------------- device scratch ----------------
__device__ float g_om [BB*27*HWSZ];
__device__ float g_y1 [BB*COUT*HWSZ];
__device__ __half g_W0h[128*K1TOT];
__device__ __half g_W1h[COUT*K1TOT];
__device__ __half g_W2h[4*COUT*K2TOT];
__device__ float g_st1[2*COUT];
__device__ float g_st2[2*COUT];
__device__ float g_p1s1[COUT*NC1];
__device__ float g_p1s2[COUT*NC1];
__device__ float g_p2s1[COUT*NC2];
__device__ float g_p2s2[COUT*NC2];

// ---------------- common helpers ----------------
__device__ __forceinline__ unsigned smem_u32(const void* p) {
    unsigned a;
    asm("{.reg .u64 t; cvta.to.shared.u64 t,%1; cvt.u32.u64 %0,t;}" : "=r"(a) : "l"(p));
    return a;
}
__device__ __forceinline__ unsigned pk2h(float a, float b) {
    __half2 h = __floats2half2_rn(a, b);
    return *(unsigned*)&h;
}
__device__ __forceinline__ void cpa16(unsigned dst, const void* src) {
    asm volatile("cp.async.cg.shared.global [%0],[%1],16;" :: "r"(dst), "l"(src));
}
__device__ __forceinline__ void cpa_wait() {
    asm volatile("cp.async.commit_group;" ::: "memory");
    asm volatile("cp.async.wait_group 0;" ::: "memory");
}

#if HAS_TC05
// ---------------- tcgen05 helpers ----------------
__device__ __forceinline__ bool elect1() {
    unsigned r;
    asm volatile("{\n\t.reg .pred p;\n\telect.sync _|p,0xFFFFFFFF;\n\tselp.b32 %0,1,0,p;\n\t}" : "=r"(r));
    return r != 0;
}
__device__ __forceinline__ void mbar_init(unsigned a, unsigned c) {
    asm volatile("mbarrier.init.shared.b64 [%0],%1;" :: "r"(a), "r"(c) : "memory");
}
__device__ __forceinline__ void mbar_wait(unsigned a, unsigned p) {
    asm volatile("{\n\t.reg .pred P;\n\tLW%=:\n\t"
                 "mbarrier.try_wait.parity.acquire.cta.shared::cta.b64 P,[%0],%1;\n\t"
                 "@!P bra LW%=;\n\t}" :: "r"(a), "r"(p) : "memory");
}
__device__ __forceinline__ void tm_alloc(unsigned saddr, unsigned n) {
    asm volatile("tcgen05.alloc.cta_group::1.sync.aligned.shared::cta.b32 [%0],%1;"
                 :: "r"(saddr), "r"(n) : "memory");
}
__device__ __forceinline__ void tm_relinq() {
    asm volatile("tcgen05.relinquish_alloc_permit.cta_group::1.sync.aligned;");
}
__device__ __forceinline__ void tm_dealloc(unsigned b, unsigned n) {
    asm volatile("tcgen05.dealloc.cta_group::1.sync.aligned.b32 %0,%1;" :: "r"(b), "r"(n));
}
__device__ __forceinline__ unsigned long long mkdesc(unsigned addr) {
    return (2ull << 61) | (1ull << 46) | (64ull << 32) | (1ull << 16)
         | ((unsigned long long)(addr >> 4) & 0x3FFF);
}
__device__ __forceinline__ void mma_ss(unsigned d, unsigned long long a, unsigned long long b, unsigned en) {
    asm volatile("{\n\t.reg .pred p;\n\tsetp.ne.u32 p,%4,0;\n\t"
                 "tcgen05.mma.cta_group::1.kind::f16 [%0], %1, %2, %3, {%5,%5,%5,%5}, p;\n\t}"
                 :: "r"(d), "l"(a), "l"(b), "r"(IDESC_F16), "r"(en), "r"(0u) : "memory");
}
__device__ __forceinline__ void tc_commit(unsigned mb) {
    asm volatile("tcgen05.commit.cta_group::1.mbarrier::arrive::one.shared::cluster.b64 [%0];"
                 :: "r"(mb) : "memory");
}
__device__ __forceinline__ void fence_async() {
    asm volatile("fence.proxy.async.shared::cta;" ::: "memory");
}
__device__ __forceinline__ void tc_fence_after()  { asm volatile("tcgen05.fence::after_thread_sync;"  ::: "memory"); }
__device__ __forceinline__ void tc_fence_before() { asm volatile("tcgen05.fence::before_thread_sync;" ::: "memory"); }
__device__ __forceinline__ void ldtm_wait() { asm volatile("tcgen05.wait::ld.sync.aligned;" ::: "memory"); }

#define LDTM32(r, addr) \
    asm volatile("tcgen05.ld.sync.aligned.32x32b.x32.b32 " \
        "{%0,%1,%2,%3,%4,%5,%6,%7,%8,%9,%10,%11,%12,%13,%14,%15," \
        "%16,%17,%18,%19,%20,%21,%22,%23,%24,%25,%26,%27,%28,%29,%30,%31},[%32];" \
        : "=r"((r)[0]),"=r"((r)[1]),"=r"((r)[2]),"=r"((r)[3]),"=r"((r)[4]),"=r"((r)[5]),"=r"((r)[6]),"=r"((r)[7]), \
          "=r"((r)[8]),"=r"((r)[9]),"=r"((r)[10]),"=r"((r)[11]),"=r"((r)[12]),"=r"((r)[13]),"=r"((r)[14]),"=r"((r)[15]), \
          "=r"((r)[16]),"=r"((r)[17]),"=r"((r)[18]),"=r"((r)[19]),"=r"((r)[20]),"=r"((r)[21]),"=r"((r)[22]),"=r"((r)[23]), \
          "=r"((r)[24]),"=r"((r)[25]),"=r"((r)[26]),"=r"((r)[27]),"=r"((r)[28]),"=r"((r)[29]),"=r"((r)[30]),"=r"((r)[31]) \
        : "r"(addr))
#else
// ---------------- fallback helpers (never selected on GB300) ----------------
__device__ __forceinline__ void ldm4(unsigned addr, unsigned r[4]) {
    asm volatile("ldmatrix.sync.aligned.m8n8.x4.shared.b16 {%0,%1,%2,%3},[%4];"
                 : "=r"(r[0]), "=r"(r[1]), "=r"(r[2]), "=r"(r[3]) : "r"(addr));
}
__device__ __forceinline__ void mma16816(float c[4], const unsigned a[4], unsigned b0, unsigned b1) {
    asm volatile("mma.sync.aligned.m16n8k16.row.col.f32.f16.f16.f32 "
                 "{%0,%1,%2,%3},{%4,%5,%6,%7},{%8,%9},{%0,%1,%2,%3};"
                 : "+f"(c[0]), "+f"(c[1]), "+f"(c[2]), "+f"(c[3])
                 : "r"(a[0]), "r"(a[1]), "r"(a[2]), "r"(a[3]), "r"(b0), "r"(b1));
}
#endif

// ---------------- weight prep (+ zero partials for fallback atomics) ----------------
__global__ void prep1_kernel(const float* __restrict__ dcn_w, const float* __restrict__ off_w) {
    int n1 = COUT*K1TOT;
    for (int idx = blockIdx.x*blockDim.x + threadIdx.x; idx < n1; idx += gridDim.x*blockDim.x) {
        int oc = idx / K1TOT;
        int kp = idx - oc*K1TOT;
        int tap = kp >> 8;
        int c   = kp & 255;
        g_W1h[idx] = __float2half(dcn_w[oc*K1TOT + c*9 + tap]);
    }
    int n0 = 128*K1TOT;
    for (int idx = blockIdx.x*blockDim.x + threadIdx.x; idx < n0; idx += gridDim.x*blockDim.x) {
        int oc = idx / K1TOT;
        int kp = idx - oc*K1TOT;
        int tap = kp >> 8;
        int c   = kp & 255;
        float v = (oc < 27) ? off_w[oc*K1TOT + c*9 + tap] : 0.f;
        g_W0h[idx] = __float2half(v);
    }
#if !HAS_TC05
    for (int idx = blockIdx.x*blockDim.x + threadIdx.x; idx < COUT*NC1; idx += gridDim.x*blockDim.x) {
        g_p1s1[idx] = 0.f; g_p1s2[idx] = 0.f;
    }
#endif
}
__global__ void prep2_kernel(const float* __restrict__ up_w) {
    int n2 = 4*COUT*K2TOT;
    for (int idx = blockIdx.x*blockDim.x + threadIdx.x; idx < n2; idx += gridDim.x*blockDim.x) {
        int pc = idx >> 16;
        int rem = idx & 65535;
        int o = rem >> 9;
        int k = rem & 511;
        int c = k >> 2, th = (k >> 1) & 1, tw = k & 1;
        int ph = pc >> 1, pw = pc & 1;
        g_W2h[idx] = __float2half(up_w[((c*COUT + o)*4 + (ph + 2*th))*4 + (pw + 2*tw)]);
    }
#if !HAS_TC05
    for (int idx = blockIdx.x*blockDim.x + threadIdx.x; idx < COUT*NC2; idx += gridDim.x*blockDim.x) {
        g_p2s1[idx] = 0.f; g_p2s2[idx] = 0.f;
    }
#endif
}

// ---------------- offset conv: tcgen05 fp16 GEMM, M=128 (27 used) ----------------
#define O_A    1024
#define O_B    33792
#define O_SMEM 50176

__global__ __launch_bounds__(256) void offconv_kernel(const float* __restrict__ x,
                                                      const float* __restrict__ off_w,
                                                      const float* __restrict__ off_b) {
#if HAS_TC05
    extern __shared__ __align__(1024) char sm[];
    int h = blockIdx.x, b = blockIdx.y;
    int tid = threadIdx.x, wid = tid >> 5, lane = tid & 31;
    unsigned sbase = smem_u32(sm);

    if (wid == 0) { tm_alloc(sbase, 64); tm_relinq(); }
    if (tid == 0) { mbar_init(sbase + 16, 1); mbar_init(sbase + 24, 1); }
    __syncthreads();
    unsigned tmem;
    asm volatile("ld.shared.b32 %0,[%1];" : "=r"(tmem) : "r"(sbase));

    unsigned ph0 = 0, ph1 = 0;
    int px = tid & 63, kb = (tid >> 6) * 16;

    for (int ch = 0; ch < 36; ch++) {
        int buf = ch & 1;
        if (ch >= 2) {
            if (buf) { mbar_wait(sbase + 24, ph1); ph1 ^= 1; }
            else     { mbar_wait(sbase + 16, ph0); ph0 ^= 1; }
        }
        int k0 = ch * 64;
        unsigned abh = sbase + O_A + (unsigned)buf*16384u;
        for (int idx = tid; idx < 1024; idx += 256) {
            int row = idx >> 3, g = idx & 7;
            unsigned so = SWZ((unsigned)(row*128 + g*16));
            cpa16(abh + so, g_W0h + row*K1TOT + k0 + g*8);
        }
        unsigned bplane = (unsigned)buf*8192u;
        int tap = ch >> 2;
        int dy = tap/3 - 1, dx = tap - (tap/3)*3 - 1;
        int hh = h + dy, ww = px + dx;
        bool ok = (hh >= 0) && (hh < HH) && (ww >= 0) && (ww < WW);
        int c0 = (k0 & 255) + kb;
        const float* xc0 = x + ((size_t)b*CIN + c0)*HWSZ + hh*WW + ww;
#pragma unroll
        for (int half = 0; half < 2; half++) {
            float v[8];
#pragma unroll
            for (int j = 0; j < 8; j++)
                v[j] = ok ? xc0[(half*8 + j)*HWSZ] : 0.f;
#pragma unroll
            for (int g = 0; g < 2; g++) {
                unsigned so = SWZ((unsigned)(px*128 + (kb + half*8 + 4*g)*2));
                *(uint2*)(sm + (O_B + bplane + so)) =
                    make_uint2(pk2h(v[4*g], v[4*g+1]), pk2h(v[4*g+2], v[4*g+3]));
            }
        }
        cpa_wait();
        fence_async();
        __syncthreads();
        if (wid == 0 && elect1()) {
            unsigned long long dAh = mkdesc(abh);
            unsigned long long dBh = mkdesc(sbase + O_B + bplane);
#pragma unroll
            for (int ks = 0; ks < 4; ks++)
                mma_ss(tmem, dAh + ks*2, dBh + ks*2, (ch | ks) ? 1u : 0u);
            tc_commit(sbase + 16 + 8*buf);
        }
    }
    mbar_wait(sbase + 16, ph0);
    mbar_wait(sbase + 24, ph1);
    tc_fence_after();
    if (wid == 0) {
        unsigned r0[32], r1[32];
        LDTM32(r0, tmem);
        LDTM32(r1, tmem + 32);
        ldtm_wait();
        int oc = lane;
        if (oc < 27) {
            float bias = off_b[oc];
            float* p = g_om + (((size_t)b*27 + oc)*HH + h)*WW;
#pragma unroll
            for (int c = 0; c < 32; c++) {
                p[c]      = __uint_as_float(r0[c]) + bias;
                p[32 + c] = __uint_as_float(r1[c]) + bias;
            }
        }
    }
    tc_fence_before();
    __syncthreads();
    if (wid == 0) tm_dealloc(tmem, 64);
#else
    // -------- fallback: scalar fp32 --------
    __shared__ float xs[8][3][66];
    __shared__ float ws[2048];
    int h = blockIdx.x, b = blockIdx.y;
    int tid = threadIdx.x;
    int w  = tid & 63;
    int ty = tid >> 6;
    float acc[7];
#pragma unroll
    for (int i = 0; i < 7; i++) acc[i] = 0.f;

    for (int c0 = 0; c0 < CIN; c0 += 8) {
        for (int idx = tid; idx < 8*198; idx += 256) {
            int cl = idx / 198; int rem = idx - cl*198;
            int r = rem / 66;   int j = rem - r*66;
            int hh = h - 1 + r; int wwp = j - 1;
            float v = 0.f;
            if (hh >= 0 && hh < HH && wwp >= 0 && wwp < WW)
                v = x[((b*CIN + c0 + cl)*HH + hh)*WW + wwp];
            xs[cl][r][j] = v;
        }
        for (int idx = tid; idx < 8*243; idx += 256) {
            int cl = idx / 243; int t = idx - cl*243;
            ws[cl*243 + t] = off_w[((t/9)*CIN + c0 + cl)*9 + (t % 9)];
        }
        __syncthreads();
#pragma unroll
        for (int cl = 0; cl < 8; cl++) {
#pragma unroll
            for (int k2 = 0; k2 < 9; k2++) {
                float xv = xs[cl][k2/3][w + (k2 % 3)];
#pragma unroll
                for (int i = 0; i < 7; i++) {
                    int oc = ty + 4*i;
                    acc[i] += ws[cl*243 + oc*9 + k2] * xv;
                }
            }
        }
        __syncthreads();
    }
#pragma unroll
    for (int i = 0; i < 7; i++) {
        int oc = ty + 4*i;
        if (oc < 27)
            g_om[((b*27 + oc)*HH + h)*WW + w] = acc[i] + off_b[oc];
    }
#endif
}

// ---------------- mdcn: 2 rows per CTA, fp16, double-buffered, tap-major, fused bn1 ----------------
// smem: [0]=tmem ptr, [16],[24]=mbar, si4@32 (2x576x8=9216), swt4@9248 (2x576x16=18432),
//       A@28672 (2buf x 16384), B@61440 (2buf x 2row x 8192). total 94208
#define M_SI   32
#define M_SWT  9248
#define M_A    28672
#define M_B    61440
#define M_SMEM 94208

__global__ __launch_bounds__(256)
void mdcn_kernel(const float* __restrict__ x, const float* __restrict__ dcn_b) {
#if HAS_TC05
    extern __shared__ __align__(1024) char sm[];
    ushort4* si4 = (ushort4*)(sm + M_SI);
    float4*  swt4 = (float4*)(sm + M_SWT);

    int h0 = blockIdx.x * 2, b = blockIdx.y;
    int tid = threadIdx.x, wid = tid >> 5, lane = tid & 31;
    unsigned sbase = smem_u32(sm);

    if (wid == 0) { tm_alloc(sbase, 128); tm_relinq(); }
    if (tid == 0) { mbar_init(sbase + 16, 1); mbar_init(sbase + 24, 1); }

    for (int s = tid; s < 1152; s += 256) {
        int row = (s >= 576) ? 1 : 0;
        int rem = s - row*576;
        int k2 = rem >> 6, px = rem & 63;
        int h = h0 + row;
        const float* omb = g_om + (size_t)b*27*HWSZ + h*WW + px;
        float dy = omb[(2*k2)    * HWSZ];
        float dx = omb[(2*k2 + 1)* HWSZ];
        float mv = 1.f / (1.f + expf(-omb[(18 + k2)*HWSZ]));
        float py  = (float)h + (float)(k2/3 - 1) + dy;
        float pxf = (float)px + (float)(k2%3 - 1) + dx;
        float y0f = floorf(py), x0f = floorf(pxf);
        float ly = py - y0f, lx = pxf - x0f;
        int y0 = (int)y0f, x0 = (int)x0f;
        int y1i = y0 + 1, x1i = x0 + 1;
        bool vy0 = (y0  >= 0) && (y0  < HH);
        bool vy1 = (y1i >= 0) && (y1i < HH);
        bool vx0 = (x0  >= 0) && (x0  < WW);
        bool vx1 = (x1i >= 0) && (x1i < WW);
        int cy0 = min(max(y0, 0), HH-1), cy1 = min(max(y1i, 0), HH-1);
        int cx0 = min(max(x0, 0), WW-1), cx1 = min(max(x1i, 0), WW-1);
        ushort4 iv;
        iv.x = (unsigned short)(cy0*WW + cx0);
        iv.y = (unsigned short)(cy0*WW + cx1);
        iv.z = (unsigned short)(cy1*WW + cx0);
        iv.w = (unsigned short)(cy1*WW + cx1);
        si4[s] = iv;
        float4 wv;
        wv.x = (1.f - ly)*(1.f - lx) * ((vy0 && vx0) ? mv : 0.f);
        wv.y = (1.f - ly)*lx         * ((vy0 && vx1) ? mv : 0.f);
        wv.z = ly*(1.f - lx)         * ((vy1 && vx0) ? mv : 0.f);
        wv.w = ly*lx                 * ((vy1 && vx1) ? mv : 0.f);
        swt4[s] = wv;
    }
    __syncthreads();
    unsigned tmem;
    asm volatile("ld.shared.b32 %0,[%1];" : "=r"(tmem) : "r"(sbase));

    const float* xb = x + (size_t)b*CIN*HWSZ;
    unsigned ph0p = 0, ph1p = 0;
    int px = tid & 63, kb = (tid >> 6) * 16;

    for (int ch = 0; ch < 36; ch++) {
        int buf = ch & 1;
        if (ch >= 2) {
            if (buf) { mbar_wait(sbase + 24, ph1p); ph1p ^= 1; }
            else     { mbar_wait(sbase + 16, ph0p); ph0p ^= 1; }
        }
        int k0 = ch * 64;
        unsigned abh = sbase + M_A + (unsigned)buf*16384u;
        for (int idx = tid; idx < 1024; idx += 256) {
            int row = idx >> 3, g = idx & 7;
            unsigned so = SWZ((unsigned)(row*128 + g*16));
            cpa16(abh + so, g_W1h + row*K1TOT + k0 + g*8);
        }
        unsigned bplane = (unsigned)buf*16384u;
        int tap = ch >> 2;
        int c0  = (k0 & 255) + kb;
        const float* xc0 = xb + c0*HWSZ;
#pragma unroll
        for (int row = 0; row < 2; row++) {
            int s = row*576 + (tap << 6) + px;
            ushort4 iv = si4[s];
            float4  wv = swt4[s];
#pragma unroll
            for (int half = 0; half < 2; half++) {
                float q0[8], q1[8], q2[8], q3[8];
#pragma unroll
                for (int j = 0; j < 8; j++) {
                    const float* xc = xc0 + (half*8 + j)*HWSZ;
                    q0[j] = xc[iv.x];
                    q1[j] = xc[iv.y];
                    q2[j] = xc[iv.z];
                    q3[j] = xc[iv.w];
                }
                float v[8];
#pragma unroll
                for (int j = 0; j < 8; j++)
                    v[j] = wv.x*q0[j] + wv.y*q1[j] + wv.z*q2[j] + wv.w*q3[j];
#pragma unroll
                for (int g = 0; g < 2; g++) {
                    unsigned so = SWZ((unsigned)(px*128 + (kb + half*8 + 4*g)*2));
                    *(uint2*)(sm + (M_B + bplane + (unsigned)row*8192u + so)) =
                        make_uint2(pk2h(v[4*g], v[4*g+1]), pk2h(v[4*g+2], v[4*g+3]));
                }
            }
        }
        cpa_wait();
        fence_async();
        __syncthreads();
        if (wid == 0 && elect1()) {
            unsigned long long dAh = mkdesc(abh);
#pragma unroll
            for (int row = 0; row < 2; row++) {
                unsigned long long dBh = mkdesc(sbase + M_B + bplane + (unsigned)row*8192u);
                unsigned dacc = tmem + (unsigned)(row*64);
#pragma unroll
                for (int ks = 0; ks < 4; ks++)
                    mma_ss(dacc, dAh + ks*2, dBh + ks*2, (ch | ks) ? 1u : 0u);
            }
            tc_commit(sbase + 16 + 8*buf);
        }
    }
    mbar_wait(sbase + 16, ph0p);
    mbar_wait(sbase + 24, ph1p);
    tc_fence_after();
    if (wid < 4) {
        int oc = wid*32 + lane;
        float bias = dcn_b[oc];
        float s1 = 0.f, s2 = 0.f;
#pragma unroll
        for (int row = 0; row < 2; row++) {
            float* p = g_y1 + (((size_t)b*COUT + oc)*HH + h0 + row)*WW;
            unsigned r0[32], r1[32];
            LDTM32(r0, tmem + (unsigned)(row*64));
            LDTM32(r1, tmem + (unsigned)(row*64) + 32);
            ldtm_wait();
#pragma unroll
            for (int q = 0; q < 8; q++) {
                float4 w0, w1;
                w0.x = __uint_as_float(r0[4*q+0]) + bias;
                w0.y = __uint_as_float(r0[4*q+1]) + bias;
                w0.z = __uint_as_float(r0[4*q+2]) + bias;
                w0.w = __uint_as_float(r0[4*q+3]) + bias;
                w1.x = __uint_as_float(r1[4*q+0]) + bias;
                w1.y = __uint_as_float(r1[4*q+1]) + bias;
                w1.z = __uint_as_float(r1[4*q+2]) + bias;
                w1.w = __uint_as_float(r1[4*q+3]) + bias;
                s1 += w0.x + w0.y + w0.z + w0.w + w1.x + w1.y + w1.z + w1.w;
                s2 += w0.x*w0.x + w0.y*w0.y + w0.z*w0.z + w0.w*w0.w
                    + w1.x*w1.x + w1.y*w1.y + w1.z*w1.z + w1.w*w1.w;
                *(float4*)&p[4*q]      = w0;
                *(float4*)&p[32 + 4*q] = w1;
            }
        }
        int cta = b*(HH/2) + blockIdx.x;
        g_p1s1[oc*NC1 + cta] = s1;
        g_p1s2[oc*NC1 + cta] = s2;
    }
    tc_fence_before();
    __syncthreads();
    if (wid == 0) tm_dealloc(tmem, 128);
#else
    // -------- fallback: mma.sync f16 (tap-major), 2 rows sequentially --------
    extern __shared__ __align__(16) char smx[];
    int*   si  = (int*)smx;
    float* swt = (float*)(smx + 9216);
    __half* Ah = (__half*)(smx + 18432);
    __half* Bh = (__half*)(smx + 55296);

    int h0 = blockIdx.x * 2, b = blockIdx.y;
    int tid = threadIdx.x;
    int wid = tid >> 5, lane = tid & 31;
    int m0 = (wid >> 1) * 32;
    int n0 = (wid & 1) * 32;
    int li = lane >> 3, lr = lane & 7;
    unsigned sAh = smem_u32(Ah);
    unsigned sBh = smem_u32(Bh);
    const float* xb = x + (size_t)b*CIN*HWSZ;

    for (int rowi = 0; rowi < 2; rowi++) {
        int h = h0 + rowi;
        __syncthreads();
        for (int s = tid; s < 576; s += 256) {
            int k2 = s >> 6, px = s & 63;
            const float* omb = g_om + (size_t)b*27*HWSZ + h*WW + px;
            float dy = omb[(2*k2)    * HWSZ];
            float dx = omb[(2*k2 + 1)* HWSZ];
            float mv = 1.f / (1.f + expf(-omb[(18 + k2)*HWSZ]));
            float py  = (float)h + (float)(k2/3 - 1) + dy;
            float pxf = (float)px + (float)(k2%3 - 1) + dx;
            float y0f = floorf(py), x0f = floorf(pxf);
            float ly = py - y0f, lx = pxf - x0f;
            int y0 = (int)y0f, x0 = (int)x0f;
            int y1i = y0 + 1, x1i = x0 + 1;
            bool vy0 = (y0  >= 0) && (y0  < HH);
            bool vy1 = (y1i >= 0) && (y1i < HH);
            bool vx0 = (x0  >= 0) && (x0  < WW);
            bool vx1 = (x1i >= 0) && (x1i < WW);
            int cy0 = min(max(y0, 0), HH-1), cy1 = min(max(y1i, 0), HH-1);
            int cx0 = min(max(x0, 0), WW-1), cx1 = min(max(x1i, 0), WW-1);
            si[0*576 + s] = cy0*WW + cx0;  si[1*576 + s] = cy0*WW + cx1;
            si[2*576 + s] = cy1*WW + cx0;  si[3*576 + s] = cy1*WW + cx1;
            swt[0*576 + s] = (1.f - ly)*(1.f - lx) * ((vy0 && vx0) ? mv : 0.f);
            swt[1*576 + s] = (1.f - ly)*lx         * ((vy0 && vx1) ? mv : 0.f);
            swt[2*576 + s] = ly*(1.f - lx)         * ((vy1 && vx0) ? mv : 0.f);
            swt[3*576 + s] = ly*lx                 * ((vy1 && vx1) ? mv : 0.f);
        }
        __syncthreads();

        float acc[2][4][4];
#pragma unroll
        for (int i = 0; i < 2; i++)
#pragma unroll
            for (int j = 0; j < 4; j++)
#pragma unroll
                for (int q = 0; q < 4; q++) acc[i][j][q] = 0.f;

        for (int ch = 0; ch < K1TOT/64; ch++) {
            int k0 = ch * 64;
            __syncthreads();
            for (int idx = tid; idx < 2048; idx += 256) {
                int row = idx >> 4, part = idx & 15;
                *(uint2*)&Ah[row*SK + part*4] = *(const uint2*)&g_W1h[row*K1TOT + k0 + part*4];
            }
            for (int idx = tid; idx < 4096; idx += 256) {
                int kk = idx >> 6, px = idx & 63;
                int k = k0 + kk;
                int tap = k >> 8;
                int c = k & 255;
                int s = (tap << 6) + px;
                const float* xc = xb + c*HWSZ;
                float v = swt[s]*xc[si[s]] + swt[576+s]*xc[si[576+s]]
                        + swt[1152+s]*xc[si[1152+s]] + swt[1728+s]*xc[si[1728+s]];
                Bh[px*SK + kk] = __float2half(v);
            }
            __syncthreads();
#pragma unroll
            for (int ks = 0; ks < 4; ks++) {
                int kbx = ks * 16;
                unsigned ah[2][4], bhf[8];
#pragma unroll
                for (int mt = 0; mt < 2; mt++) {
                    int row = m0 + mt*16 + ((li & 1) << 3) + lr;
                    int col = kbx + ((li >> 1) << 3);
                    ldm4(sAh + (unsigned)(row*SK + col)*2, ah[mt]);
                }
#pragma unroll
                for (int jj = 0; jj < 2; jj++) {
                    int row = n0 + jj*16 + ((li >> 1) << 3) + lr;
                    int col = kbx + ((li & 1) << 3);
                    ldm4(sBh + (unsigned)(row*SK + col)*2, &bhf[jj*4]);
                }
#pragma unroll
                for (int mt = 0; mt < 2; mt++)
#pragma unroll
                    for (int j = 0; j < 4; j++)
                        mma16816(acc[mt][j], ah[mt], bhf[2*j], bhf[2*j+1]);
            }
        }

        int g = lane >> 2, tg = lane & 3;
        int cta = b*(HH/2) + blockIdx.x;
#pragma unroll
        for (int mt = 0; mt < 2; mt++) {
            int ocA = m0 + mt*16 + g;
            int ocB = ocA + 8;
            float bzA = dcn_b[ocA], bzB = dcn_b[ocB];
            float* pA = g_y1 + ((size_t)(b*COUT + ocA)*HH + h)*WW;
            float* pB = g_y1 + ((size_t)(b*COUT + ocB)*HH + h)*WW;
            float sA1 = 0.f, sA2 = 0.f, sB1 = 0.f, sB2 = 0.f;
#pragma unroll
            for (int j = 0; j < 4; j++) {
                int w = n0 + j*8 + tg*2;
                float2 vA = {acc[mt][j][0] + bzA, acc[mt][j][1] + bzA};
                float2 vB = {acc[mt][j][2] + bzB, acc[mt][j][3] + bzB};
                sA1 += vA.x + vA.y; sA2 += vA.x*vA.x + vA.y*vA.y;
                sB1 += vB.x + vB.y; sB2 += vB.x*vB.x + vB.y*vB.y;
                *(float2*)&pA[w] = vA;
                *(float2*)&pB[w] = vB;
            }
            atomicAdd(&g_p1s1[ocA*NC1 + cta], sA1);
            atomicAdd(&g_p1s2[ocA*NC1 + cta], sA2);
            atomicAdd(&g_p1s1[ocB*NC1 + cta], sB1);
            atomicAdd(&g_p1s2[ocB*NC1 + cta], sB2);
        }
    }
#endif
}

// ---------------- deconv: fp16, parity in grid, fused bn2 partials ----------------
#define D_SCS  32
#define D_SHS  544
#define D_A    2048
#define D_B    34816
#define D_SMEM 56320

__global__ __launch_bounds__(256)
void deconv_kernel(float* __restrict__ out,
                   const float* __restrict__ bn1_g, const float* __restrict__ bn1_b) {
#if HAS_TC05
    extern __shared__ __align__(1024) char sm[];
    float* scs = (float*)(sm + D_SCS);
    float* shs = (float*)(sm + D_SHS);

    int par = blockIdx.x, oh = blockIdx.y, b = blockIdx.z;
    int phh = (oh + 1) & 1;
    int pw  = (par + 1) & 1;
    int pc  = phh*2 + pw;
    int IH0 = (oh + 1 - phh) >> 1;
    int tid = threadIdx.x, wid = tid >> 5, lane = tid & 31;
    unsigned sbase = smem_u32(sm);

    if (wid == 0) { tm_alloc(sbase, 128); tm_relinq(); }
    if (tid == 0) { mbar_init(sbase + 16, 1); mbar_init(sbase + 24, 1); }
    if (tid < COUT) {
        float sc = g_st1[COUT + tid] * bn1_g[tid];
        scs[tid] = sc;
        shs[tid] = bn1_b[tid] - g_st1[tid]*sc;
    }
    __syncthreads();
    unsigned tmem;
    asm volatile("ld.shared.b32 %0,[%1];" : "=r"(tmem) : "r"(sbase));

    const float* yb = g_y1 + (size_t)b*COUT*HWSZ;
    const __half* W2h = g_W2h + (size_t)pc*COUT*K2TOT;
    unsigned ph0 = 0, ph1 = 0;
    int px = tid & 63, kb = (tid >> 6) * 16;

    for (int ch = 0; ch < 8; ch++) {
        int buf = ch & 1;
        if (ch >= 2) {
            if (buf) { mbar_wait(sbase + 24, ph1); ph1 ^= 1; }
            else     { mbar_wait(sbase + 16, ph0); ph0 ^= 1; }
        }
        int k0 = ch * 64;
        unsigned abh = sbase + D_A + (unsigned)buf*16384u;
        for (int idx = tid; idx < 1024; idx += 256) {
            int row = idx >> 3, g = idx & 7;
            unsigned so = SWZ((unsigned)(row*128 + g*16));
            cpa16(abh + so, W2h + row*K2TOT + k0 + g*8);
        }
        unsigned bplane = (unsigned)buf*8192u;
#pragma unroll
        for (int half = 0; half < 2; half++) {
            float v[8];
#pragma unroll
            for (int j = 0; j < 8; j++) {
                int k = k0 + kb + half*8 + j;
                int cl = k >> 2, th = (k >> 1) & 1, tw = k & 1;
                int ih = IH0 - th;
                int iw = px + par - tw;
                bool ok = (ih >= 0) && (ih < HH) && (iw >= 0) && (iw < WW);
                float q = ok ? yb[cl*HWSZ + ih*WW + iw] : 0.f;
                float t = q*scs[cl] + shs[cl];
                v[j] = ok ? fmaxf(t, 0.f) : 0.f;
            }
#pragma unroll
            for (int g = 0; g < 2; g++) {
                unsigned so = SWZ((unsigned)(px*128 + (kb + half*8 + 4*g)*2));
                *(uint2*)(sm + (D_B + bplane + so)) =
                    make_uint2(pk2h(v[4*g], v[4*g+1]), pk2h(v[4*g+2], v[4*g+3]));
            }
        }
        cpa_wait();
        fence_async();
        __syncthreads();
        if (wid == 0 && elect1()) {
            unsigned long long dAh = mkdesc(abh);
            unsigned long long dBh = mkdesc(sbase + D_B + bplane);
#pragma unroll
            for (int ks = 0; ks < 4; ks++)
                mma_ss(tmem, dAh + ks*2, dBh + ks*2, (ch | ks) ? 1u : 0u);
            tc_commit(sbase + 16 + 8*buf);
        }
    }
    mbar_wait(sbase + 16, ph0);
    mbar_wait(sbase + 24, ph1);
    tc_fence_after();
    if (wid < 4) {
        unsigned r0[32], r1[32];
        LDTM32(r0, tmem);
        LDTM32(r1, tmem + 32);
        ldtm_wait();
        int oc = wid*32 + lane;
        float* p = out + (((size_t)b*COUT + oc)*OHH + oh)*OWW + par;
        float s1 = 0.f, s2 = 0.f;
#pragma unroll
        for (int c = 0; c < 32; c++) {
            float a0 = __uint_as_float(r0[c]);
            float a1 = __uint_as_float(r1[c]);
            s1 += a0 + a1;
            s2 += a0*a0 + a1*a1;
            p[2*c]        = a0;
            p[2*(32 + c)] = a1;
        }
        int cta = (b*OHH + oh)*2 + par;
        g_p2s1[oc*NC2 + cta] = s1;
        g_p2s2[oc*NC2 + cta] = s2;
    }
    tc_fence_before();
    __syncthreads();
    if (wid == 0) tm_dealloc(tmem, 128);
#else
    // -------- fallback: mma.sync f16 --------
    extern __shared__ __align__(16) char smx[];
    float* scs = (float*)smx;
    float* shs = (float*)(smx + 512);
    __half* Ah = (__half*)(smx + 1024);
    __half* Bh = (__half*)(smx + 37888);

    int par = blockIdx.x;
    int oh = blockIdx.y, b = blockIdx.z;
    int ph = (oh + 1) & 1;
    int pw = (par + 1) & 1;
    int pc = ph*2 + pw;
    int IH0 = (oh + 1 - ph) >> 1;
    int tid = threadIdx.x;
    int wid = tid >> 5, lane = tid & 31;
    int m0 = (wid >> 1) * 32;
    int n0 = (wid & 1) * 32;

    if (tid < COUT) {
        float sc = g_st1[COUT + tid] * bn1_g[tid];
        scs[tid] = sc;
        shs[tid] = bn1_b[tid] - g_st1[tid]*sc;
    }

    const float* yb = g_y1 + (size_t)b*COUT*HWSZ;
    const __half* W2h = g_W2h + (size_t)pc*COUT*K2TOT;
    unsigned sAh = smem_u32(Ah);
    unsigned sBh = smem_u32(Bh);

    float acc[2][4][4];
#pragma unroll
    for (int i = 0; i < 2; i++)
#pragma unroll
        for (int j = 0; j < 4; j++)
#pragma unroll
            for (int q = 0; q < 4; q++) acc[i][j][q] = 0.f;

    int li = lane >> 3, lr = lane & 7;
    __syncthreads();

    for (int ch = 0; ch < K2TOT/64; ch++) {
        int k0 = ch * 64;
        if (ch) __syncthreads();
        for (int idx = tid; idx < 2048; idx += 256) {
            int row = idx >> 4, part = idx & 15;
            *(uint2*)&Ah[row*SK + part*4] = *(const uint2*)&W2h[row*K2TOT + k0 + part*4];
        }
        for (int idx = tid; idx < 4096; idx += 256) {
            int kk = idx >> 6, px = idx & 63;
            int k = k0 + kk;
            int cl = k >> 2, th = (k >> 1) & 1, tw = k & 1;
            int ih = IH0 - th;
            int iw = px + par - tw;
            float v = 0.f;
            if (ih >= 0 && ih < HH && iw >= 0 && iw < WW)
                v = fmaxf(yb[cl*HWSZ + ih*WW + iw]*scs[cl] + shs[cl], 0.f);
            Bh[px*SK + kk] = __float2half(v);
        }
        __syncthreads();
#pragma unroll
        for (int ks = 0; ks < 4; ks++) {
            int kbx = ks * 16;
            unsigned ah[2][4], bhf[8];
#pragma unroll
            for (int mt = 0; mt < 2; mt++) {
                int row = m0 + mt*16 + ((li & 1) << 3) + lr;
                int col = kbx + ((li >> 1) << 3);
                ldm4(sAh + (unsigned)(row*SK + col)*2, ah[mt]);
            }
#pragma unroll
            for (int jj = 0; jj < 2; jj++) {
                int row = n0 + jj*16 + ((li >> 1) << 3) + lr;
                int col = kbx + ((li & 1) << 3);
                ldm4(sBh + (unsigned)(row*SK + col)*2, &bhf[jj*4]);
            }
#pragma unroll
            for (int mt = 0; mt < 2; mt++)
#pragma unroll
                for (int j = 0; j < 4; j++)
                    mma16816(acc[mt][j], ah[mt], bhf[2*j], bhf[2*j+1]);
        }
    }

    int g = lane >> 2, tg = lane & 3;
    int cta = (b*OHH + oh)*2 + par;
#pragma unroll
    for (int mt = 0; mt < 2; mt++) {
        int ocA = m0 + mt*16 + g;
        int ocB = ocA + 8;
        float* pA = out + ((size_t)(b*COUT + ocA)*OHH + oh)*OWW;
        float* pB = out + ((size_t)(b*COUT + ocB)*OHH + oh)*OWW;
        float sA1 = 0.f, sA2 = 0.f, sB1 = 0.f, sB2 = 0.f;
#pragma unroll
        for (int j = 0; j < 4; j++) {
            int pxx = n0 + j*8 + tg*2;
            int ow = par + 2*pxx;
            float a0 = acc[mt][j][0], a1 = acc[mt][j][1];
            float b0 = acc[mt][j][2], b1 = acc[mt][j][3];
            sA1 += a0 + a1; sA2 += a0*a0 + a1*a1;
            sB1 += b0 + b1; sB2 += b0*b0 + b1*b1;
            pA[ow]     = a0;
            pA[ow + 2] = a1;
            pB[ow]     = b0;
            pB[ow + 2] = b1;
        }
        atomicAdd(&g_p2s1[ocA*NC2 + cta], sA1);
        atomicAdd(&g_p2s2[ocA*NC2 + cta], sA2);
        atomicAdd(&g_p2s1[ocB*NC2 + cta], sB1);
        atomicAdd(&g_p2s2[ocB*NC2 + cta], sB2);
    }
#endif
}

// ---------------- bn finalize from per-CTA partials ----------------
__global__ __launch_bounds__(256) void bn_fin_kernel(const float* __restrict__ s1a,
                                                     const float* __restrict__ s2a,
                                                     float* __restrict__ stats,
                                                     int n, float cnt) {
    int c = blockIdx.x;
    float s1 = 0.f, s2 = 0.f;
    for (int i = threadIdx.x; i < n; i += 256) {
        s1 += s1a[c*n + i];
        s2 += s2a[c*n + i];
    }
    __shared__ float r1[8], r2[8];
#pragma unroll
    for (int off = 16; off; off >>= 1) {
        s1 += __shfl_down_sync(~0u, s1, off);
        s2 += __shfl_down_sync(~0u, s2, off);
    }
    int lane = threadIdx.x & 31, wid = threadIdx.x >> 5;
    if (lane == 0) { r1[wid] = s1; r2[wid] = s2; }
    __syncthreads();
    if (wid == 0 && lane < 8) {
        s1 = r1[lane]; s2 = r2[lane];
#pragma unroll
        for (int off = 4; off; off >>= 1) {
            s1 += __shfl_down_sync(0xffu, s1, off);
            s2 += __shfl_down_sync(0xffu, s2, off);
        }
        if (lane == 0) {
            float mean = s1 / cnt;
            float var  = s2 / cnt - mean*mean;
            stats[c]        = mean;
            stats[COUT + c] = rsqrtf(var + 1e-5f);
        }
    }
}

// ---------------- bn apply + relu: flat 1D, one float4/thread ----------------
__global__ __launch_bounds__(256) void bn_apply_kernel(float* __restrict__ x,
                                                       const float* __restrict__ stats,
                                                       const float* __restrict__ g,
                                                       const float* __restrict__ bta) {
    int i = blockIdx.x*256 + threadIdx.x;
    int c = (i >> 12) & (COUT - 1);
    float sc = stats[COUT + c] * g[c];
    float sh = bta[c] - stats[c] * sc;
    float4* p = (float4*)x;
    float4 v = p[i];
    v.x = fmaxf(v.x*sc + sh, 0.f);
    v.y = fmaxf(v.y*sc + sh, 0.f);
    v.z = fmaxf(v.z*sc + sh, 0.f);
    v.w = fmaxf(v.w*sc + sh, 0.f);
    p[i] = v;
}

// ---------------- launch ----------------
extern "C" void kernel_launch(void* const* d_in, const int* in_sizes, int n_in,
                              void* d_out, int out_size) {
    const float* x     = (const float*)d_in[0];
    const float* off_w = (const float*)d_in[1];
    const float* off_b = (const float*)d_in[2];
    const float* dcn_w = (const float*)d_in[3];
    const float* dcn_b = (const float*)d_in[4];
    const float* bn1_g = (const float*)d_in[5];
    const float* bn1_b = (const float*)d_in[6];
    const float* up_w  = (const float*)d_in[7];
    const float* bn2_g = (const float*)d_in[8];
    const float* bn2_b = (const float*)d_in[9];
    float* out = (float*)d_out;

    float *st1p, *st2p, *p1s1, *p1s2, *p2s1, *p2s2;
    cudaGetSymbolAddress((void**)&st1p, g_st1);
    cudaGetSymbolAddress((void**)&st2p, g_st2);
    cudaGetSymbolAddress((void**)&p1s1, g_p1s1);
    cudaGetSymbolAddress((void**)&p1s2, g_p1s2);
    cudaGetSymbolAddress((void**)&p2s1, g_p2s1);
    cudaGetSymbolAddress((void**)&p2s2, g_p2s2);

    cudaFuncSetAttribute(offconv_kernel, cudaFuncAttributeMaxDynamicSharedMemorySize, O_SMEM);
    cudaFuncSetAttribute(mdcn_kernel,    cudaFuncAttributeMaxDynamicSharedMemorySize, M_SMEM);
    cudaFuncSetAttribute(deconv_kernel,  cudaFuncAttributeMaxDynamicSharedMemorySize, D_SMEM);

    prep1_kernel<<<128, 256>>>(dcn_w, off_w);
    prep2_kernel<<<128, 256>>>(up_w);
    offconv_kernel<<<dim3(HH, BB), 256, O_SMEM>>>(x, off_w, off_b);
    mdcn_kernel<<<dim3(HH/2, BB), 256, M_SMEM>>>(x, dcn_b);
    bn_fin_kernel<<<COUT, 256>>>(p1s1, p1s2, st1p, NC1, (float)(BB*HWSZ));
    deconv_kernel<<<dim3(2, OHH, BB), 256, D_SMEM>>>(out, bn1_g, bn1_b);
    bn_fin_kernel<<<COUT, 256>>>(p2s1, p2s2, st2p, NC2, (float)(BB*OHW));
    bn_apply_kernel<<<(BB*COUT*OHW/4 + 255)/256, 256>>>(out, st2p, bn2_g, bn2_b);
}